// round 1
// baseline (speedup 1.0000x reference)
#include <cuda_runtime.h>

#define NP      8
#define NP1     9      // n_p + 1
#define IN_D    10     // n_p + 2
#define LAT     128
#define TILE_E  64
#define THREADS 128

// Packed dual-fp32 FMA (SASS FFMA2) — only reachable via PTX fma.rn.f32x2.
__device__ __forceinline__ float2 ffma2f(float2 a, float2 b, float2 c) {
    float2 d;
    asm("fma.rn.f32x2 %0, %1, %2, %3;"
        : "=l"(*reinterpret_cast<unsigned long long*>(&d))
        : "l"(*reinterpret_cast<unsigned long long*>(&a)),
          "l"(*reinterpret_cast<unsigned long long*>(&b)),
          "l"(*reinterpret_cast<unsigned long long*>(&c)));
    return d;
}

__device__ __forceinline__ float4 relu4(float4 v) {
    v.x = fmaxf(v.x, 0.f); v.y = fmaxf(v.y, 0.f);
    v.z = fmaxf(v.z, 0.f); v.w = fmaxf(v.w, 0.f);
    return v;
}

// Dense layer IN_DIM -> 128 over a 64-element tile.
// sIn:  transposed activations [IN_DIM][64] in SMEM
// sOut: transposed activations [128][64] in SMEM
// Thread tile: 8 elements x 8 neurons. 128 threads = 8 egroups x 16 jgroups.
template <int IN_DIM, bool RELU>
__device__ __forceinline__ void dense128(const float* __restrict__ W,
                                         const float* __restrict__ b,
                                         const float* __restrict__ sIn,
                                         float* __restrict__ sOut,
                                         int tid)
{
    const int e0 = (tid & 7) * 8;
    const int j0 = (tid >> 3) * 8;

    float2 acc[8][4];
    {
        const float4 bv0 = __ldg(reinterpret_cast<const float4*>(b + j0));
        const float4 bv1 = __ldg(reinterpret_cast<const float4*>(b + j0 + 4));
        float2 bp[4] = {{bv0.x, bv0.y}, {bv0.z, bv0.w}, {bv1.x, bv1.y}, {bv1.z, bv1.w}};
        #pragma unroll
        for (int e = 0; e < 8; e++)
            #pragma unroll
            for (int jp = 0; jp < 4; jp++)
                acc[e][jp] = bp[jp];
    }

    #pragma unroll 2
    for (int i = 0; i < IN_DIM; i++) {
        const float4 w0 = __ldg(reinterpret_cast<const float4*>(W + i * LAT + j0));
        const float4 w1 = __ldg(reinterpret_cast<const float4*>(W + i * LAT + j0 + 4));
        float2 wp[4] = {{w0.x, w0.y}, {w0.z, w0.w}, {w1.x, w1.y}, {w1.z, w1.w}};

        const float4 a0 = *reinterpret_cast<const float4*>(sIn + i * TILE_E + e0);
        const float4 a1 = *reinterpret_cast<const float4*>(sIn + i * TILE_E + e0 + 4);
        const float av[8] = {a0.x, a0.y, a0.z, a0.w, a1.x, a1.y, a1.z, a1.w};

        #pragma unroll
        for (int e = 0; e < 8; e++) {
            const float2 ad = make_float2(av[e], av[e]);
            #pragma unroll
            for (int jp = 0; jp < 4; jp++)
                acc[e][jp] = ffma2f(ad, wp[jp], acc[e][jp]);
        }
    }

    // Store transposed: row j across elements e0..e0+7.
    #pragma unroll
    for (int jp = 0; jp < 4; jp++) {
        const int j = j0 + 2 * jp;
        float4 vx0 = make_float4(acc[0][jp].x, acc[1][jp].x, acc[2][jp].x, acc[3][jp].x);
        float4 vx1 = make_float4(acc[4][jp].x, acc[5][jp].x, acc[6][jp].x, acc[7][jp].x);
        float4 vy0 = make_float4(acc[0][jp].y, acc[1][jp].y, acc[2][jp].y, acc[3][jp].y);
        float4 vy1 = make_float4(acc[4][jp].y, acc[5][jp].y, acc[6][jp].y, acc[7][jp].y);
        if (RELU) { vx0 = relu4(vx0); vx1 = relu4(vx1); vy0 = relu4(vy0); vy1 = relu4(vy1); }
        *reinterpret_cast<float4*>(sOut + j * TILE_E + e0)           = vx0;
        *reinterpret_cast<float4*>(sOut + j * TILE_E + e0 + 4)       = vx1;
        *reinterpret_cast<float4*>(sOut + (j + 1) * TILE_E + e0)     = vy0;
        *reinterpret_cast<float4*>(sOut + (j + 1) * TILE_E + e0 + 4) = vy1;
    }
}

__global__ void __launch_bounds__(THREADS)
ElementGNN_kernel(const float* __restrict__ data,
                  const int*   __restrict__ elements,
                  const float* __restrict__ W0, const float* __restrict__ b0,
                  const float* __restrict__ W1, const float* __restrict__ b1,
                  const float* __restrict__ W2, const float* __restrict__ b2,
                  const float* __restrict__ W3, const float* __restrict__ b3,
                  const float* __restrict__ W4, const float* __restrict__ b4,
                  const float* __restrict__ W5, const float* __restrict__ b5,
                  const float* __restrict__ W6, const float* __restrict__ b6,
                  float* __restrict__ out, int k)
{
    extern __shared__ float sm[];
    float* s_sent = sm;                         // [10][64]
    float* actA   = sm + IN_D * TILE_E;         // [128][64]
    float* actB   = actA + LAT * TILE_E;        // [128][64]

    const int tid  = threadIdx.x;
    const int base = blockIdx.x * TILE_E;

    // ---- Gather: sent = [d2[left,-1], d2[e,:], d2[right,0]] transposed into SMEM ----
    for (int t = tid; t < IN_D * TILE_E; t += THREADS) {
        const int le = t & (TILE_E - 1);
        const int i  = t >> 6;                  // 0..9
        float v = 0.f;
        const int pos = base + le;
        if (pos < k) {
            const int e = elements[pos] / NP1;
            if (i == 0) {
                int left = e - 1; if (left < 0) left += k;
                v = __ldg(data + left * NP + (NP - 1));
            } else if (i == IN_D - 1) {
                int right = e + 1; if (right >= k) right -= k;
                v = __ldg(data + right * NP);
            } else {
                v = __ldg(data + e * NP + (i - 1));
            }
        }
        s_sent[i * TILE_E + le] = v;
    }
    __syncthreads();

    // ---- MLP trunk ----
    dense128<IN_D, true >(W0, b0, s_sent, actA, tid); __syncthreads();
    dense128<LAT,  false>(W1, b1, actA,   actB, tid); __syncthreads();
    dense128<LAT,  true >(W2, b2, actB,   actA, tid); __syncthreads();
    dense128<LAT,  false>(W3, b3, actA,   actB, tid); __syncthreads();

    // ---- Tail: 128->8 (relu), 8->8, 8->10, residual, write cols 1..8 ----
    if (tid < TILE_E) {
        const int le = tid;

        float h[NP];
        #pragma unroll
        for (int j = 0; j < NP; j++) h[j] = __ldg(b4 + j);

        #pragma unroll 4
        for (int i = 0; i < LAT; i++) {
            const float a = actB[i * TILE_E + le];
            const float4 w0 = __ldg(reinterpret_cast<const float4*>(W4 + i * NP));
            const float4 w1 = __ldg(reinterpret_cast<const float4*>(W4 + i * NP + 4));
            h[0] = fmaf(a, w0.x, h[0]); h[1] = fmaf(a, w0.y, h[1]);
            h[2] = fmaf(a, w0.z, h[2]); h[3] = fmaf(a, w0.w, h[3]);
            h[4] = fmaf(a, w1.x, h[4]); h[5] = fmaf(a, w1.y, h[5]);
            h[6] = fmaf(a, w1.z, h[6]); h[7] = fmaf(a, w1.w, h[7]);
        }
        #pragma unroll
        for (int j = 0; j < NP; j++) h[j] = fmaxf(h[j], 0.f);

        float g[NP];
        #pragma unroll
        for (int j = 0; j < NP; j++) g[j] = __ldg(b5 + j);
        #pragma unroll
        for (int i = 0; i < NP; i++) {
            const float hv = h[i];
            #pragma unroll
            for (int j = 0; j < NP; j++)
                g[j] = fmaf(hv, __ldg(W5 + i * NP + j), g[j]);
        }

        float res[NP];
        #pragma unroll
        for (int j = 1; j <= NP; j++) {
            float f = __ldg(b6 + j);
            #pragma unroll
            for (int i = 0; i < NP; i++)
                f = fmaf(g[i], __ldg(W6 + i * IN_D + j), f);
            res[j - 1] = s_sent[j * TILE_E + le] + f;
        }

        const int pos = base + le;
        if (pos < k) {
            float4* op = reinterpret_cast<float4*>(out + (size_t)pos * NP);
            op[0] = make_float4(res[0], res[1], res[2], res[3]);
            op[1] = make_float4(res[4], res[5], res[6], res[7]);
        }
    }
}

extern "C" void kernel_launch(void* const* d_in, const int* in_sizes, int n_in,
                              void* d_out, int out_size)
{
    const float* data     = (const float*)d_in[0];
    const int*   elements = (const int*)  d_in[1];
    const float* W0 = (const float*)d_in[2];  const float* b0 = (const float*)d_in[3];
    const float* W1 = (const float*)d_in[4];  const float* b1 = (const float*)d_in[5];
    const float* W2 = (const float*)d_in[6];  const float* b2 = (const float*)d_in[7];
    const float* W3 = (const float*)d_in[8];  const float* b3 = (const float*)d_in[9];
    const float* W4 = (const float*)d_in[10]; const float* b4 = (const float*)d_in[11];
    const float* W5 = (const float*)d_in[12]; const float* b5 = (const float*)d_in[13];
    const float* W6 = (const float*)d_in[14]; const float* b6 = (const float*)d_in[15];
    float* out = (float*)d_out;

    const int k = in_sizes[1];
    const int grid = (k + TILE_E - 1) / TILE_E;
    const size_t smem = (size_t)(IN_D * TILE_E + 2 * LAT * TILE_E) * sizeof(float);

    cudaFuncSetAttribute(ElementGNN_kernel,
                         cudaFuncAttributeMaxDynamicSharedMemorySize, (int)smem);

    ElementGNN_kernel<<<grid, THREADS, smem>>>(
        data, elements, W0, b0, W1, b1, W2, b2, W3, b3, W4, b4, W5, b5, W6, b6,
        out, k);
}

// round 3
// speedup vs baseline: 2.4158x; 2.4158x over previous
#include <cuda_runtime.h>
#include <cuda_bf16.h>
#include <stdint.h>

#define NP      8
#define NP1     9
#define IN_D    10
#define THREADS 256
#define TILE_M  128

// Fragment-ordered weight images: [layer][ (ntg*NKS+ks)*32 + lane ]*16B = {wh0,wh1,wl0,wl1}
// layer0: NKS=1 (8KB used), layers1-3: NKS=8 (64KB)
__device__ __align__(16) unsigned char g_W[4][65536];

// ---------------- helpers ----------------
__device__ __forceinline__ uint32_t smem_u32(const void* p){
    uint32_t a;
    asm("{ .reg .u64 t; cvta.to.shared.u64 t, %1; cvt.u32.u64 %0, t; }" : "=r"(a) : "l"(p));
    return a;
}
__device__ __forceinline__ uint32_t packbf(float x0, float x1){ // x0 -> low half
    uint32_t r; asm("cvt.rn.bf16x2.f32 %0, %1, %2;" : "=r"(r) : "f"(x1), "f"(x0)); return r;
}
__device__ __forceinline__ float bflo(uint32_t u){ return __uint_as_float(u<<16); }
__device__ __forceinline__ float bfhi(uint32_t u){ return __uint_as_float(u & 0xFFFF0000u); }

#define MBAR_INIT(a,c)   asm volatile("mbarrier.init.shared.b64 [%0], %1;" :: "r"(a), "r"(c) : "memory")
#define MBAR_EXPECT(a,b) asm volatile("mbarrier.arrive.expect_tx.shared.b64 _, [%0], %1;" :: "r"(a), "r"(b) : "memory")
#define FENCE_PROXY()    asm volatile("fence.proxy.async.shared::cta;" ::: "memory")

__device__ __forceinline__ void mbar_wait(uint32_t mbar, uint32_t parity){
    asm volatile(
        "{\n\t.reg .pred P;\n\t"
        "WL_%=:\n\t"
        "mbarrier.try_wait.parity.acquire.cta.shared::cta.b64 P, [%0], %1, 0x989680;\n\t"
        "@P bra.uni WD_%=;\n\t"
        "bra.uni WL_%=;\n\t"
        "WD_%=:\n\t}"
        :: "r"(mbar), "r"(parity) : "memory");
}
__device__ __forceinline__ void bulk_copy(uint32_t dst, const void* src, uint32_t bytes, uint32_t mbar){
    asm volatile(
        "cp.async.bulk.shared::cta.global.mbarrier::complete_tx::bytes [%0], [%1], %2, [%3];"
        :: "r"(dst), "l"(src), "r"(bytes), "r"(mbar) : "memory");
}

#define LDS128(r0,r1,r2,r3,addr) \
    asm volatile("ld.shared.v4.b32 {%0,%1,%2,%3}, [%4];" : "=r"(r0),"=r"(r1),"=r"(r2),"=r"(r3) : "r"(addr))
#define STS128(addr,r0,r1,r2,r3) \
    asm volatile("st.shared.v4.b32 [%0], {%1,%2,%3,%4};" :: "r"(addr),"r"(r0),"r"(r1),"r"(r2),"r"(r3) : "memory")
#define LDS32(r,addr) \
    asm volatile("ld.shared.b32 %0, [%1];" : "=r"(r) : "r"(addr))
#define STS32(addr,r) \
    asm volatile("st.shared.b32 [%0], %1;" :: "r"(addr), "r"(r) : "memory")

__device__ __forceinline__ void mma_bf16(float& c0, float& c1, float& c2, float& c3,
                                         uint32_t a0, uint32_t a1, uint32_t a2, uint32_t a3,
                                         uint32_t b0, uint32_t b1){
    asm volatile(
        "mma.sync.aligned.m16n8k16.row.col.f32.bf16.bf16.f32 "
        "{%0,%1,%2,%3}, {%4,%5,%6,%7}, {%8,%9}, {%0,%1,%2,%3};"
        : "+f"(c0), "+f"(c1), "+f"(c2), "+f"(c3)
        : "r"(a0), "r"(a1), "r"(a2), "r"(a3), "r"(b0), "r"(b1));
}

// ---------------- weight prep: fragment-ordered hi/lo images ----------------
__global__ void prep_kernel(const float* __restrict__ W0, const float* __restrict__ W1,
                            const float* __restrict__ W2, const float* __restrict__ W3)
{
    const int layer = blockIdx.y;
    const int NKS   = (layer == 0) ? 1 : 8;
    const int idx   = blockIdx.x * 256 + threadIdx.x;   // (ntg*NKS+ks)*32 + lane
    if (idx >= 16 * NKS * 32) return;

    const int lane = idx & 31;
    const int fs   = idx >> 5;          // ntg*NKS + ks
    const int ks   = fs % NKS;
    const int ntg  = fs / NKS;
    const int g    = lane >> 2;
    const int t    = lane & 3;
    const int n    = ntg * 8 + g;
    const int kb   = ks * 16;

    const float* W = (layer == 0) ? W0 : (layer == 1) ? W1 : (layer == 2) ? W2 : W3;
    const int KMAX = (layer == 0) ? IN_D : 128;

    float v[4];
    const int krow[4] = { kb + 2*t, kb + 2*t + 1, kb + 2*t + 8, kb + 2*t + 9 };
    #pragma unroll
    for (int i = 0; i < 4; i++)
        v[i] = (krow[i] < KMAX) ? __ldg(W + krow[i] * 128 + n) : 0.f;

    uint32_t wh0, wh1, wl0, wl1;
    {
        float h0 = bfhi(packbf(v[0], v[0]));  // bf16-round via pack trick? use direct:
        // direct hi/lo split
        __nv_bfloat16 bh0 = __float2bfloat16(v[0]);
        __nv_bfloat16 bh1 = __float2bfloat16(v[1]);
        __nv_bfloat16 bh2 = __float2bfloat16(v[2]);
        __nv_bfloat16 bh3 = __float2bfloat16(v[3]);
        float f0 = __bfloat162float(bh0), f1 = __bfloat162float(bh1);
        float f2 = __bfloat162float(bh2), f3 = __bfloat162float(bh3);
        wh0 = packbf(f0, f1);
        wh1 = packbf(f2, f3);
        wl0 = packbf(v[0] - f0, v[1] - f1);
        wl1 = packbf(v[2] - f2, v[3] - f3);
        (void)h0;
    }
    uint4* dst = (uint4*)(&g_W[layer][(size_t)idx * 16]);
    *dst = make_uint4(wh0, wh1, wl0, wl1);
}

// ---------------- per-layer MMA loop ----------------
template <int NKS>
__device__ __forceinline__ void run_layer(float acc[2][8][4],
                                          uint32_t aHi, uint32_t aLo, uint32_t wB,
                                          int lane, int mg, int ng)
{
    const uint32_t a0h = aHi + (2*mg)     * 8 * 512 + lane * 16;
    const uint32_t a1h = aHi + (2*mg + 1) * 8 * 512 + lane * 16;
    const uint32_t a0l = aLo + (2*mg)     * 8 * 512 + lane * 16;
    const uint32_t a1l = aLo + (2*mg + 1) * 8 * 512 + lane * 16;
    const uint32_t wBase = wB + (uint32_t)(ng * 8 * NKS) * 512 + lane * 16;

    #pragma unroll
    for (int ks = 0; ks < NKS; ks++) {
        uint32_t ah0[4], al0[4], ah1[4], al1[4];
        LDS128(ah0[0],ah0[1],ah0[2],ah0[3], a0h + ks*512);
        LDS128(al0[0],al0[1],al0[2],al0[3], a0l + ks*512);
        LDS128(ah1[0],ah1[1],ah1[2],ah1[3], a1h + ks*512);
        LDS128(al1[0],al1[1],al1[2],al1[3], a1l + ks*512);

        #pragma unroll
        for (int nt = 0; nt < 8; nt++) {
            uint32_t w0, w1, w2, w3;
            LDS128(w0, w1, w2, w3, wBase + (uint32_t)(nt * NKS + ks) * 512);
            mma_bf16(acc[0][nt][0],acc[0][nt][1],acc[0][nt][2],acc[0][nt][3],
                     ah0[0],ah0[1],ah0[2],ah0[3], w0, w1);
            mma_bf16(acc[0][nt][0],acc[0][nt][1],acc[0][nt][2],acc[0][nt][3],
                     al0[0],al0[1],al0[2],al0[3], w0, w1);
            mma_bf16(acc[0][nt][0],acc[0][nt][1],acc[0][nt][2],acc[0][nt][3],
                     ah0[0],ah0[1],ah0[2],ah0[3], w2, w3);
            mma_bf16(acc[1][nt][0],acc[1][nt][1],acc[1][nt][2],acc[1][nt][3],
                     ah1[0],ah1[1],ah1[2],ah1[3], w0, w1);
            mma_bf16(acc[1][nt][0],acc[1][nt][1],acc[1][nt][2],acc[1][nt][3],
                     al1[0],al1[1],al1[2],al1[3], w0, w1);
            mma_bf16(acc[1][nt][0],acc[1][nt][1],acc[1][nt][2],acc[1][nt][3],
                     ah1[0],ah1[1],ah1[2],ah1[3], w2, w3);
        }
    }
}

// ---------------- epilogue: D frags + bias (+relu) -> next-layer A frags ----------------
template <bool RELU>
__device__ __forceinline__ void epilogue(float acc[2][8][4],
                                         uint32_t aHi, uint32_t aLo,
                                         const float* __restrict__ sBiasL,
                                         int lane, int mg, int ng)
{
    float bb[8][2];
    #pragma unroll
    for (int nt = 0; nt < 8; nt++) {
        const float* bp = sBiasL + (ng*64 + nt*8 + (lane & 3)*2);
        bb[nt][0] = bp[0]; bb[nt][1] = bp[1];
    }
    #pragma unroll
    for (int mt2 = 0; mt2 < 2; mt2++) {
        #pragma unroll
        for (int q = 0; q < 4; q++) {
            const int ntE = 2*q, ntO = 2*q + 1;
            float x[8];
            x[0] = acc[mt2][ntE][0] + bb[ntE][0];
            x[1] = acc[mt2][ntE][1] + bb[ntE][1];
            x[2] = acc[mt2][ntE][2] + bb[ntE][0];
            x[3] = acc[mt2][ntE][3] + bb[ntE][1];
            x[4] = acc[mt2][ntO][0] + bb[ntO][0];
            x[5] = acc[mt2][ntO][1] + bb[ntO][1];
            x[6] = acc[mt2][ntO][2] + bb[ntO][0];
            x[7] = acc[mt2][ntO][3] + bb[ntO][1];
            if (RELU) {
                #pragma unroll
                for (int i = 0; i < 8; i++) x[i] = fmaxf(x[i], 0.f);
            }
            uint32_t H[4], L[4];
            #pragma unroll
            for (int i = 0; i < 4; i++) {
                H[i] = packbf(x[2*i], x[2*i+1]);
                L[i] = packbf(x[2*i] - bflo(H[i]), x[2*i+1] - bfhi(H[i]));
            }
            const int kt = ng*4 + q;
            const int mt = 2*mg + mt2;
            const uint32_t off = (uint32_t)(mt*8 + kt) * 512 + lane * 16;
            STS128(aHi + off, H[0], H[1], H[2], H[3]);
            STS128(aLo + off, L[0], L[1], L[2], L[3]);
        }
    }
}

__device__ __forceinline__ void zero_acc(float acc[2][8][4]){
    #pragma unroll
    for (int a = 0; a < 2; a++)
        #pragma unroll
        for (int b = 0; b < 8; b++)
            #pragma unroll
            for (int c = 0; c < 4; c++) acc[a][b][c] = 0.f;
}

// ---------------- main kernel ----------------
__global__ void __launch_bounds__(THREADS, 1)
ElementGNN_mma_kernel(const float* __restrict__ data,
                      const int*   __restrict__ elements,
                      const float* __restrict__ b0, const float* __restrict__ b1,
                      const float* __restrict__ b2, const float* __restrict__ b3,
                      const float* __restrict__ W4, const float* __restrict__ b4,
                      const float* __restrict__ W5, const float* __restrict__ b5,
                      const float* __restrict__ W6, const float* __restrict__ b6,
                      float* __restrict__ out, int k)
{
    extern __shared__ char smraw[];
    const uint32_t raw = smem_u32(smraw);
    const uint32_t s0  = (raw + 1023u) & ~1023u;
    char* base = smraw + (s0 - raw);

    const uint32_t aHi   = s0;                    // 32KB  A frags (hi)
    const uint32_t aLo   = s0 + 32768u;           // 32KB  A frags (lo)
    const uint32_t wBuf0 = s0 + 65536u;           // 64KB
    const uint32_t wBuf1 = s0 + 131072u;          // 64KB
    float* sent  = (float*)(base + 196608);       // [128][8] fp32
    float* sBias = (float*)(base + 200704);       // [4][128]
    const uint32_t bar0 = s0 + 202752u;
    const uint32_t bar1 = s0 + 202760u;
    float* sPart = (float*)(base + 65536);        // tail partials (alias wBuf0, 4KB)
    float* sW4   = (float*)(base + 65536 + 8192); // W4 [128][8] (alias wBuf0+8KB)

    const int tid  = threadIdx.x;
    const int lane = tid & 31;
    const int warp = tid >> 5;
    const int mg   = warp & 3;
    const int ng   = warp >> 2;
    const int basE = blockIdx.x * TILE_M;

    if (tid == 0) {
        MBAR_INIT(bar0, 1);
        MBAR_INIT(bar1, 1);
        FENCE_PROXY();
    }
    __syncthreads();
    if (tid == 0) {
        MBAR_EXPECT(bar0, 8192u);  bulk_copy(wBuf0, &g_W[0][0], 8192u,  bar0);
        MBAR_EXPECT(bar1, 65536u); bulk_copy(wBuf1, &g_W[1][0], 65536u, bar1);
    }

    // bias table
    if (tid < 128) {
        sBias[0*128 + tid] = __ldg(b0 + tid);
        sBias[1*128 + tid] = __ldg(b1 + tid);
        sBias[2*128 + tid] = __ldg(b2 + tid);
        sBias[3*128 + tid] = __ldg(b3 + tid);
    }

    // ---- gather -> layer0 A frags (kt=0), residual sent ----
    {
        const int m    = tid & 127;
        const int half = tid >> 7;      // 0 -> hi plane, 1 -> lo plane
        const int pos  = basE + m;
        float v[IN_D];
        #pragma unroll
        for (int j = 0; j < IN_D; j++) v[j] = 0.f;
        if (pos < k) {
            const int e  = elements[pos] / NP1;
            const int le = (e == 0) ? (k - 1) : (e - 1);
            const int ri = (e == k - 1) ? 0 : (e + 1);
            const float4 a0 = __ldg((const float4*)(data + (size_t)e * NP));
            const float4 a1 = __ldg((const float4*)(data + (size_t)e * NP + 4));
            v[0] = __ldg(data + (size_t)le * NP + (NP - 1));
            v[1] = a0.x; v[2] = a0.y; v[3] = a0.z; v[4] = a0.w;
            v[5] = a1.x; v[6] = a1.y; v[7] = a1.z; v[8] = a1.w;
            v[9] = __ldg(data + (size_t)ri * NP);
        }
        if (half == 0) {
            float4* sp = (float4*)(sent + m * 8);
            sp[0] = make_float4(v[1], v[2], v[3], v[4]);
            sp[1] = make_float4(v[5], v[6], v[7], v[8]);
        }
        const int mt = m >> 4, rh = (m & 15) >> 3, g7 = m & 7;
        const uint32_t planeB = (half ? aLo : aHi) + (uint32_t)(mt * 8) * 512;
        #pragma unroll
        for (int p = 0; p < 8; p++) {
            const float x0 = (2*p   < IN_D) ? v[2*p]   : 0.f;
            const float x1 = (2*p+1 < IN_D) ? v[2*p+1] : 0.f;
            const uint32_t H = packbf(x0, x1);
            const uint32_t word = half ? packbf(x0 - bflo(H), x1 - bfhi(H)) : H;
            const int reg   = ((p < 4) ? 0 : 2) + rh;
            const int lane2 = g7 * 4 + (p & 3);
            STS32(planeB + (uint32_t)lane2 * 16 + (uint32_t)reg * 4, word);
        }
    }
    __syncthreads();

    float acc[2][8][4];

    // ---- layer 0 (K=16, relu) ----
    mbar_wait(bar0, 0);
    zero_acc(acc);
    run_layer<1>(acc, aHi, aLo, wBuf0, lane, mg, ng);
    __syncthreads();
    if (tid == 0) { MBAR_EXPECT(bar0, 65536u); bulk_copy(wBuf0, &g_W[2][0], 65536u, bar0); }
    epilogue<true>(acc, aHi, aLo, sBias + 0*128, lane, mg, ng);
    __syncthreads();

    // ---- layer 1 (K=128) ----
    mbar_wait(bar1, 0);
    zero_acc(acc);
    run_layer<8>(acc, aHi, aLo, wBuf1, lane, mg, ng);
    __syncthreads();
    if (tid == 0) { MBAR_EXPECT(bar1, 65536u); bulk_copy(wBuf1, &g_W[3][0], 65536u, bar1); }
    epilogue<false>(acc, aHi, aLo, sBias + 1*128, lane, mg, ng);
    __syncthreads();

    // ---- layer 2 (K=128, relu) ----
    mbar_wait(bar0, 1);
    zero_acc(acc);
    run_layer<8>(acc, aHi, aLo, wBuf0, lane, mg, ng);
    __syncthreads();
    // wBuf0 now dead: stage W4 into smem for the tail
    for (int i = tid; i < 128 * 8; i += THREADS) sW4[i] = __ldg(W4 + i);
    epilogue<true>(acc, aHi, aLo, sBias + 2*128, lane, mg, ng);
    __syncthreads();

    // ---- layer 3 (K=128) ----
    mbar_wait(bar1, 1);
    zero_acc(acc);
    run_layer<8>(acc, aHi, aLo, wBuf1, lane, mg, ng);
    __syncthreads();
    epilogue<false>(acc, aHi, aLo, sBias + 3*128, lane, mg, ng);
    __syncthreads();

    // ---- tail: 128->8 relu, 8->8, 8->10, residual ----
    {
        const int m     = tid & 127;
        const int khalf = tid >> 7;
        const int mt = m >> 4, rh = (m & 15) >> 3, g7 = m & 7;

        float h[NP];
        if (khalf == 0) {
            const float4 q0 = __ldg((const float4*)(b4));
            const float4 q1 = __ldg((const float4*)(b4 + 4));
            h[0]=q0.x; h[1]=q0.y; h[2]=q0.z; h[3]=q0.w;
            h[4]=q1.x; h[5]=q1.y; h[6]=q1.z; h[7]=q1.w;
        } else {
            #pragma unroll
            for (int j = 0; j < NP; j++) h[j] = 0.f;
        }

        #pragma unroll
        for (int q = 0; q < 4; q++) {
            const int kt = khalf * 4 + q;
            const uint32_t fb = (uint32_t)(mt * 8 + kt) * 512 + (uint32_t)g7 * 64;
            #pragma unroll
            for (int c = 0; c < 4; c++) {
                uint32_t hA, hB, lA, lB;
                LDS32(hA, aHi + fb + c*16 + rh*4);
                LDS32(hB, aHi + fb + c*16 + (2 + rh)*4);
                LDS32(lA, aLo + fb + c*16 + rh*4);
                LDS32(lB, aLo + fb + c*16 + (2 + rh)*4);
                const float vv[4] = { bflo(hA) + bflo(lA), bfhi(hA) + bfhi(lA),
                                      bflo(hB) + bflo(lB), bfhi(hB) + bfhi(lB) };
                const int kk[4] = { kt*16 + 2*c, kt*16 + 2*c + 1,
                                    kt*16 + 8 + 2*c, kt*16 + 9 + 2*c };
                #pragma unroll
                for (int u = 0; u < 4; u++) {
                    const float a = vv[u];
                    const float4 w0 = *(const float4*)(sW4 + kk[u]*NP);
                    const float4 w1 = *(const float4*)(sW4 + kk[u]*NP + 4);
                    h[0] = fmaf(a, w0.x, h[0]); h[1] = fmaf(a, w0.y, h[1]);
                    h[2] = fmaf(a, w0.z, h[2]); h[3] = fmaf(a, w0.w, h[3]);
                    h[4] = fmaf(a, w1.x, h[4]); h[5] = fmaf(a, w1.y, h[5]);
                    h[6] = fmaf(a, w1.z, h[6]); h[7] = fmaf(a, w1.w, h[7]);
                }
            }
        }

        if (khalf == 1) {
            float4* pp = (float4*)(sPart + m * 8);
            pp[0] = make_float4(h[0], h[1], h[2], h[3]);
            pp[1] = make_float4(h[4], h[5], h[6], h[7]);
        }
        __syncthreads();
        if (khalf == 0) {
            const float4 p0 = *(const float4*)(sPart + m * 8);
            const float4 p1 = *(const float4*)(sPart + m * 8 + 4);
            h[0]+=p0.x; h[1]+=p0.y; h[2]+=p0.z; h[3]+=p0.w;
            h[4]+=p1.x; h[5]+=p1.y; h[6]+=p1.z; h[7]+=p1.w;
            #pragma unroll
            for (int j = 0; j < NP; j++) h[j] = fmaxf(h[j], 0.f);

            float g[NP];
            {
                const float4 q0 = __ldg((const float4*)(b5));
                const float4 q1 = __ldg((const float4*)(b5 + 4));
                g[0]=q0.x; g[1]=q0.y; g[2]=q0.z; g[3]=q0.w;
                g[4]=q1.x; g[5]=q1.y; g[6]=q1.z; g[7]=q1.w;
            }
            #pragma unroll
            for (int i = 0; i < NP; i++) {
                const float hv = h[i];
                const float4 r0 = __ldg((const float4*)(W5 + i*NP));
                const float4 r1 = __ldg((const float4*)(W5 + i*NP + 4));
                g[0]=fmaf(hv,r0.x,g[0]); g[1]=fmaf(hv,r0.y,g[1]);
                g[2]=fmaf(hv,r0.z,g[2]); g[3]=fmaf(hv,r0.w,g[3]);
                g[4]=fmaf(hv,r1.x,g[4]); g[5]=fmaf(hv,r1.y,g[5]);
                g[6]=fmaf(hv,r1.z,g[6]); g[7]=fmaf(hv,r1.w,g[7]);
            }

            float res[NP];
            #pragma unroll
            for (int j = 1; j <= NP; j++) {
                float f = __ldg(b6 + j);
                #pragma unroll
                for (int i = 0; i < NP; i++)
                    f = fmaf(g[i], __ldg(W6 + i * IN_D + j), f);
                res[j - 1] = sent[m * 8 + (j - 1)] + f;
            }

            const int pos = basE + m;
            if (pos < k) {
                float4* op = (float4*)(out + (size_t)pos * NP);
                op[0] = make_float4(res[0], res[1], res[2], res[3]);
                op[1] = make_float4(res[4], res[5], res[6], res[7]);
            }
        }
    }
}

// ---------------- launch ----------------
extern "C" void kernel_launch(void* const* d_in, const int* in_sizes, int n_in,
                              void* d_out, int out_size)
{
    const float* data     = (const float*)d_in[0];
    const int*   elements = (const int*)  d_in[1];
    const float* W0 = (const float*)d_in[2];  const float* b0 = (const float*)d_in[3];
    const float* W1 = (const float*)d_in[4];  const float* b1 = (const float*)d_in[5];
    const float* W2 = (const float*)d_in[6];  const float* b2 = (const float*)d_in[7];
    const float* W3 = (const float*)d_in[8];  const float* b3 = (const float*)d_in[9];
    const float* W4 = (const float*)d_in[10]; const float* b4 = (const float*)d_in[11];
    const float* W5 = (const float*)d_in[12]; const float* b5 = (const float*)d_in[13];
    const float* W6 = (const float*)d_in[14]; const float* b6 = (const float*)d_in[15];
    float* out = (float*)d_out;

    const int k = in_sizes[1];

    prep_kernel<<<dim3(16, 4), 256>>>(W0, W1, W2, W3);

    const int grid = (k + TILE_M - 1) / TILE_M;
    const size_t smem = 202768u + 1024u;
    cudaFuncSetAttribute(ElementGNN_mma_kernel,
                         cudaFuncAttributeMaxDynamicSharedMemorySize, (int)smem);
    ElementGNN_mma_kernel<<<grid, THREADS, smem>>>(
        data, elements, b0, b1, b2, b3, W4, b4, W5, b5, W6, b6, out, k);
}

// round 4
// speedup vs baseline: 2.7648x; 1.1445x over previous
#include <cuda_runtime.h>
#include <cuda_bf16.h>
#include <stdint.h>

#define NP      8
#define NP1     9
#define IN_D    10
#define THREADS 288          // 8 compute warps + 1 producer warp
#define TILE_M  128

// Fragment-ordered weight images per layer: [hi | lo], hi size = NKS*4KB.
// Entry ((ntp*NKS+ks)*32+lane)*16B = {w0(nt=2ntp), w1(nt=2ntp), w0(nt=2ntp+1), w1(nt=2ntp+1)}
__device__ __align__(16) unsigned char g_W[4][65536];   // L0 uses 8KB

// ---------------- helpers ----------------
__device__ __forceinline__ uint32_t smem_u32(const void* p){
    uint32_t a;
    asm("{ .reg .u64 t; cvta.to.shared.u64 t, %1; cvt.u32.u64 %0, t; }" : "=r"(a) : "l"(p));
    return a;
}
__device__ __forceinline__ uint32_t packbf(float x0, float x1){ // x0 -> low half
    uint32_t r; asm("cvt.rn.bf16x2.f32 %0, %1, %2;" : "=r"(r) : "f"(x1), "f"(x0)); return r;
}
__device__ __forceinline__ float bflo(uint32_t u){ return __uint_as_float(u<<16); }
__device__ __forceinline__ float bfhi(uint32_t u){ return __uint_as_float(u & 0xFFFF0000u); }

#define MBAR_INIT(a,c)   asm volatile("mbarrier.init.shared.b64 [%0], %1;" :: "r"(a), "r"(c) : "memory")
#define MBAR_EXPECT(a,b) asm volatile("mbarrier.arrive.expect_tx.shared.b64 _, [%0], %1;" :: "r"(a), "r"(b) : "memory")
#define MBAR_ARRIVE(a)   asm volatile("mbarrier.arrive.shared.b64 _, [%0];" :: "r"(a) : "memory")
#define FENCE_PROXY()    asm volatile("fence.proxy.async.shared::cta;" ::: "memory")

__device__ __forceinline__ void mbar_wait(uint32_t mbar, uint32_t parity){
    asm volatile(
        "{\n\t.reg .pred P;\n\t"
        "WL_%=:\n\t"
        "mbarrier.try_wait.parity.acquire.cta.shared::cta.b64 P, [%0], %1, 0x989680;\n\t"
        "@P bra.uni WD_%=;\n\t"
        "bra.uni WL_%=;\n\t"
        "WD_%=:\n\t}"
        :: "r"(mbar), "r"(parity) : "memory");
}
__device__ __forceinline__ void bulk_copy(uint32_t dst, const void* src, uint32_t bytes, uint32_t mbar){
    asm volatile(
        "cp.async.bulk.shared::cta.global.mbarrier::complete_tx::bytes [%0], [%1], %2, [%3];"
        :: "r"(dst), "l"(src), "r"(bytes), "r"(mbar) : "memory");
}

#define LDS128(r0,r1,r2,r3,addr) \
    asm volatile("ld.shared.v4.b32 {%0,%1,%2,%3}, [%4];" : "=r"(r0),"=r"(r1),"=r"(r2),"=r"(r3) : "r"(addr))

#define MMA_BF16(C, a0,a1,a2,a3, b0,b1) \
    asm volatile("mma.sync.aligned.m16n8k16.row.col.f32.bf16.bf16.f32 " \
        "{%0,%1,%2,%3}, {%4,%5,%6,%7}, {%8,%9}, {%0,%1,%2,%3};" \
        : "+f"((C)[0]), "+f"((C)[1]), "+f"((C)[2]), "+f"((C)[3]) \
        : "r"(a0), "r"(a1), "r"(a2), "r"(a3), "r"(b0), "r"(b1))

// ---------------- weight prep ----------------
__global__ void prep_kernel(const float* __restrict__ W0, const float* __restrict__ W1,
                            const float* __restrict__ W2, const float* __restrict__ W3)
{
    const int layer = blockIdx.y;
    const int NKS   = (layer == 0) ? 1 : 8;
    const int idx   = blockIdx.x * 256 + threadIdx.x;
    if (idx >= 8 * NKS * 32) return;

    const int lane = idx & 31;
    const int rest = idx >> 5;
    const int ks   = rest % NKS;
    const int ntp  = rest / NKS;
    const int n8   = lane >> 2;
    const int t    = lane & 3;

    const float* W = (layer == 0) ? W0 : (layer == 1) ? W1 : (layer == 2) ? W2 : W3;
    const int KMAX = (layer == 0) ? IN_D : 128;

    uint32_t hi[4], lo[4];
    #pragma unroll
    for (int h = 0; h < 2; h++) {
        const int n = (2*ntp + h) * 8 + n8;
        const int kb = ks * 16;
        const int kr[4] = { kb + 2*t, kb + 2*t + 1, kb + 2*t + 8, kb + 2*t + 9 };
        float v[4];
        #pragma unroll
        for (int i = 0; i < 4; i++)
            v[i] = (kr[i] < KMAX) ? __ldg(W + kr[i] * 128 + n) : 0.f;
        float f[4];
        #pragma unroll
        for (int i = 0; i < 4; i++) f[i] = __bfloat162float(__float2bfloat16(v[i]));
        hi[2*h]   = packbf(f[0], f[1]);
        hi[2*h+1] = packbf(f[2], f[3]);
        lo[2*h]   = packbf(v[0]-f[0], v[1]-f[1]);
        lo[2*h+1] = packbf(v[2]-f[2], v[3]-f[3]);
    }
    const uint32_t loOff = (uint32_t)NKS * 4096u;
    *(uint4*)(&g_W[layer][(size_t)idx * 16])         = make_uint4(hi[0],hi[1],hi[2],hi[3]);
    *(uint4*)(&g_W[layer][loOff + (size_t)idx * 16]) = make_uint4(lo[0],lo[1],lo[2],lo[3]);
}

// ---------------- per-layer MMA (register-chained) ----------------
template <int NKS>
__device__ __forceinline__ void layer_mma(float acc[16][4],
                                          const uint32_t aHi[8][4], const uint32_t aLo[8][4],
                                          uint32_t wbase, int lane)
{
    const uint32_t lof = (uint32_t)lane * 16u;
    const uint32_t loP = (uint32_t)NKS * 4096u;
    #pragma unroll
    for (int ks = 0; ks < NKS; ks++) {
        #pragma unroll
        for (int ntp = 0; ntp < 8; ntp++) {
            uint32_t w0,w1,w2,w3;
            LDS128(w0,w1,w2,w3, wbase + (uint32_t)((ntp*NKS + ks)*32)*16u + lof);
            MMA_BF16(acc[2*ntp],   aHi[ks][0],aHi[ks][1],aHi[ks][2],aHi[ks][3], w0, w1);
            MMA_BF16(acc[2*ntp],   aLo[ks][0],aLo[ks][1],aLo[ks][2],aLo[ks][3], w0, w1);
            MMA_BF16(acc[2*ntp+1], aHi[ks][0],aHi[ks][1],aHi[ks][2],aHi[ks][3], w2, w3);
            MMA_BF16(acc[2*ntp+1], aLo[ks][0],aLo[ks][1],aLo[ks][2],aLo[ks][3], w2, w3);
        }
        #pragma unroll
        for (int ntp = 0; ntp < 8; ntp++) {
            uint32_t w0,w1,w2,w3;
            LDS128(w0,w1,w2,w3, wbase + loP + (uint32_t)((ntp*NKS + ks)*32)*16u + lof);
            MMA_BF16(acc[2*ntp],   aHi[ks][0],aHi[ks][1],aHi[ks][2],aHi[ks][3], w0, w1);
            MMA_BF16(acc[2*ntp+1], aHi[ks][0],aHi[ks][1],aHi[ks][2],aHi[ks][3], w2, w3);
        }
    }
}

// D frags + bias (+relu) -> next layer A frags (pure registers); zeroes acc.
template <bool RELU>
__device__ __forceinline__ void make_A(float acc[16][4],
                                       uint32_t aHi[8][4], uint32_t aLo[8][4],
                                       const float* __restrict__ biasL, int c)
{
    #pragma unroll
    for (int kt = 0; kt < 8; kt++) {
        #pragma unroll
        for (int h = 0; h < 2; h++) {
            const int nt = 2*kt + h;
            const float b0 = biasL[nt*8 + 2*c];
            const float b1 = biasL[nt*8 + 2*c + 1];
            float x0 = acc[nt][0] + b0, x1 = acc[nt][1] + b1;
            float x2 = acc[nt][2] + b0, x3 = acc[nt][3] + b1;
            if (RELU) {
                x0 = fmaxf(x0,0.f); x1 = fmaxf(x1,0.f);
                x2 = fmaxf(x2,0.f); x3 = fmaxf(x3,0.f);
            }
            const uint32_t H0 = packbf(x0,x1), H1 = packbf(x2,x3);
            aHi[kt][2*h]   = H0;  aLo[kt][2*h]   = packbf(x0-bflo(H0), x1-bfhi(H0));
            aHi[kt][2*h+1] = H1;  aLo[kt][2*h+1] = packbf(x2-bflo(H1), x3-bfhi(H1));
            acc[nt][0]=0.f; acc[nt][1]=0.f; acc[nt][2]=0.f; acc[nt][3]=0.f;
        }
    }
}

// ---------------- main kernel ----------------
__global__ void __launch_bounds__(THREADS, 1)
ElementGNN_rc_kernel(const float* __restrict__ data,
                     const int*   __restrict__ elements,
                     const float* __restrict__ b0, const float* __restrict__ b1,
                     const float* __restrict__ b2, const float* __restrict__ b3,
                     const float* __restrict__ W4, const float* __restrict__ b4,
                     const float* __restrict__ W5, const float* __restrict__ b5,
                     const float* __restrict__ W6, const float* __restrict__ b6,
                     float* __restrict__ out, int k)
{
    extern __shared__ char smraw[];
    const uint32_t raw = smem_u32(smraw);
    const uint32_t s0  = (raw + 1023u) & ~1023u;
    char* base = smraw + (s0 - raw);

    const uint32_t wBuf0 = s0;                 // 64KB
    const uint32_t wBuf1 = s0 + 65536u;        // 64KB
    float* s_in  = (float*)(base + 131072);    // [128][12] fp32  (6144B)
    float* sBias = (float*)(base + 137216);    // [4][128]        (2048B)
    float* sW4   = (float*)(base + 139264);    // [128][8]        (4096B)
    const uint32_t full0  = s0 + 143360u;
    const uint32_t full1  = s0 + 143368u;
    const uint32_t empty0 = s0 + 143376u;
    const uint32_t empty1 = s0 + 143384u;

    const int tid  = threadIdx.x;
    const int warp = tid >> 5;
    const int lane = tid & 31;
    const int basE = blockIdx.x * TILE_M;

    if (tid == 0) {
        MBAR_INIT(full0, 1); MBAR_INIT(full1, 1);
        MBAR_INIT(empty0, 8); MBAR_INIT(empty1, 8);
        FENCE_PROXY();
    }

    // ---- gather into s_in [128][12], stage W4 + biases ----
    if (tid < 128) {
        const int m = tid, pos = basE + m;
        float v[IN_D];
        #pragma unroll
        for (int j = 0; j < IN_D; j++) v[j] = 0.f;
        if (pos < k) {
            const int e  = elements[pos] / NP1;
            const int le = (e == 0) ? (k - 1) : (e - 1);
            const int ri = (e == k - 1) ? 0 : (e + 1);
            const float4 a0 = __ldg((const float4*)(data + (size_t)e * NP));
            const float4 a1 = __ldg((const float4*)(data + (size_t)e * NP + 4));
            v[0] = __ldg(data + (size_t)le * NP + (NP - 1));
            v[1]=a0.x; v[2]=a0.y; v[3]=a0.z; v[4]=a0.w;
            v[5]=a1.x; v[6]=a1.y; v[7]=a1.z; v[8]=a1.w;
            v[9] = __ldg(data + (size_t)ri * NP);
        }
        #pragma unroll
        for (int j = 0; j < IN_D; j++) s_in[m*12 + j] = v[j];
        sBias[0*128 + m] = __ldg(b0 + m);
        sBias[1*128 + m] = __ldg(b1 + m);
        sBias[2*128 + m] = __ldg(b2 + m);
        sBias[3*128 + m] = __ldg(b3 + m);
    }
    for (int i = tid; i < 128*NP; i += THREADS) sW4[i] = __ldg(W4 + i);
    __syncthreads();

    // ---- producer warp: weight double-buffer pipeline ----
    if (warp == 8) {
        if (lane == 0) {
            MBAR_EXPECT(full0, 8192u);  bulk_copy(wBuf0, &g_W[0][0], 8192u,  full0);
            MBAR_EXPECT(full1, 65536u); bulk_copy(wBuf1, &g_W[1][0], 65536u, full1);
            mbar_wait(empty0, 0);
            MBAR_EXPECT(full0, 65536u); bulk_copy(wBuf0, &g_W[2][0], 65536u, full0);
            mbar_wait(empty1, 0);
            MBAR_EXPECT(full1, 65536u); bulk_copy(wBuf1, &g_W[3][0], 65536u, full1);
        }
        return;
    }

    // ---- compute warps: register-chained MLP ----
    const int gr = lane >> 2, c = lane & 3;
    const int r0 = warp * 16 + gr;           // local rows r0, r0+8

    uint32_t aHi[8][4], aLo[8][4];
    {   // layer-0 A frags from s_in (cols 2c,2c+1,2c+8,2c+9; >=10 are zero)
        const int cols[4] = { 2*c, 2*c+1, 2*c+8, 2*c+9 };
        float f0[4], f1[4];
        #pragma unroll
        for (int i = 0; i < 4; i++) {
            f0[i] = (cols[i] < IN_D) ? s_in[r0*12 + cols[i]]       : 0.f;
            f1[i] = (cols[i] < IN_D) ? s_in[(r0+8)*12 + cols[i]]   : 0.f;
        }
        const uint32_t H0 = packbf(f0[0], f0[1]), H1 = packbf(f1[0], f1[1]);
        const uint32_t H2 = packbf(f0[2], f0[3]), H3 = packbf(f1[2], f1[3]);
        aHi[0][0]=H0; aLo[0][0]=packbf(f0[0]-bflo(H0), f0[1]-bfhi(H0));
        aHi[0][1]=H1; aLo[0][1]=packbf(f1[0]-bflo(H1), f1[1]-bfhi(H1));
        aHi[0][2]=H2; aLo[0][2]=packbf(f0[2]-bflo(H2), f0[3]-bfhi(H2));
        aHi[0][3]=H3; aLo[0][3]=packbf(f1[2]-bflo(H3), f1[3]-bfhi(H3));
    }

    float acc[16][4];
    #pragma unroll
    for (int i = 0; i < 16; i++) { acc[i][0]=0.f; acc[i][1]=0.f; acc[i][2]=0.f; acc[i][3]=0.f; }

    // L0 (K=16, relu)
    mbar_wait(full0, 0);
    layer_mma<1>(acc, aHi, aLo, wBuf0, lane);
    __syncwarp();
    if (lane == 0) MBAR_ARRIVE(empty0);
    make_A<true>(acc, aHi, aLo, sBias + 0*128, c);

    // L1 (K=128)
    mbar_wait(full1, 0);
    layer_mma<8>(acc, aHi, aLo, wBuf1, lane);
    __syncwarp();
    if (lane == 0) MBAR_ARRIVE(empty1);
    make_A<false>(acc, aHi, aLo, sBias + 1*128, c);

    // L2 (K=128, relu)
    mbar_wait(full0, 1);
    layer_mma<8>(acc, aHi, aLo, wBuf0, lane);
    make_A<true>(acc, aHi, aLo, sBias + 2*128, c);

    // L3 (K=128)
    mbar_wait(full1, 1);
    layer_mma<8>(acc, aHi, aLo, wBuf1, lane);

    // ---- tail: bias3 + GEMV 128->8 from registers, quad reduce, scalar finish ----
    float h0[NP], h1[NP];
    #pragma unroll
    for (int j = 0; j < NP; j++) { h0[j]=0.f; h1[j]=0.f; }
    const float* bias3 = sBias + 3*128;
    #pragma unroll
    for (int nt = 0; nt < 16; nt++) {
        const float bb0 = bias3[nt*8 + 2*c], bb1 = bias3[nt*8 + 2*c + 1];
        const float xa = acc[nt][0]+bb0, xb = acc[nt][1]+bb1;
        const float xc = acc[nt][2]+bb0, xd = acc[nt][3]+bb1;
        const int col0 = nt*8 + 2*c;
        const float4 wA0 = *(const float4*)(sW4 + col0*NP);
        const float4 wA1 = *(const float4*)(sW4 + col0*NP + 4);
        const float4 wB0 = *(const float4*)(sW4 + (col0+1)*NP);
        const float4 wB1 = *(const float4*)(sW4 + (col0+1)*NP + 4);
        h0[0]=fmaf(xa,wA0.x,fmaf(xb,wB0.x,h0[0])); h0[1]=fmaf(xa,wA0.y,fmaf(xb,wB0.y,h0[1]));
        h0[2]=fmaf(xa,wA0.z,fmaf(xb,wB0.z,h0[2])); h0[3]=fmaf(xa,wA0.w,fmaf(xb,wB0.w,h0[3]));
        h0[4]=fmaf(xa,wA1.x,fmaf(xb,wB1.x,h0[4])); h0[5]=fmaf(xa,wA1.y,fmaf(xb,wB1.y,h0[5]));
        h0[6]=fmaf(xa,wA1.z,fmaf(xb,wB1.z,h0[6])); h0[7]=fmaf(xa,wA1.w,fmaf(xb,wB1.w,h0[7]));
        h1[0]=fmaf(xc,wA0.x,fmaf(xd,wB0.x,h1[0])); h1[1]=fmaf(xc,wA0.y,fmaf(xd,wB0.y,h1[1]));
        h1[2]=fmaf(xc,wA0.z,fmaf(xd,wB0.z,h1[2])); h1[3]=fmaf(xc,wA0.w,fmaf(xd,wB0.w,h1[3]));
        h1[4]=fmaf(xc,wA1.x,fmaf(xd,wB1.x,h1[4])); h1[5]=fmaf(xc,wA1.y,fmaf(xd,wB1.y,h1[5]));
        h1[6]=fmaf(xc,wA1.z,fmaf(xd,wB1.z,h1[6])); h1[7]=fmaf(xc,wA1.w,fmaf(xd,wB1.w,h1[7]));
    }
    #pragma unroll
    for (int j = 0; j < NP; j++) {
        h0[j] += __shfl_xor_sync(0xffffffffu, h0[j], 1);
        h0[j] += __shfl_xor_sync(0xffffffffu, h0[j], 2);
        h1[j] += __shfl_xor_sync(0xffffffffu, h1[j], 1);
        h1[j] += __shfl_xor_sync(0xffffffffu, h1[j], 2);
    }

    if (c == 0) {
        #pragma unroll
        for (int half = 0; half < 2; half++) {
            const float* hh = half ? h1 : h0;
            const int row = r0 + half * 8;
            const int pos = basE + row;

            float hv[NP];
            {
                const float4 q0 = __ldg((const float4*)(b4));
                const float4 q1 = __ldg((const float4*)(b4 + 4));
                hv[0]=fmaxf(hh[0]+q0.x,0.f); hv[1]=fmaxf(hh[1]+q0.y,0.f);
                hv[2]=fmaxf(hh[2]+q0.z,0.f); hv[3]=fmaxf(hh[3]+q0.w,0.f);
                hv[4]=fmaxf(hh[4]+q1.x,0.f); hv[5]=fmaxf(hh[5]+q1.y,0.f);
                hv[6]=fmaxf(hh[6]+q1.z,0.f); hv[7]=fmaxf(hh[7]+q1.w,0.f);
            }
            float g[NP];
            {
                const float4 q0 = __ldg((const float4*)(b5));
                const float4 q1 = __ldg((const float4*)(b5 + 4));
                g[0]=q0.x; g[1]=q0.y; g[2]=q0.z; g[3]=q0.w;
                g[4]=q1.x; g[5]=q1.y; g[6]=q1.z; g[7]=q1.w;
            }
            #pragma unroll
            for (int i = 0; i < NP; i++) {
                const float x = hv[i];
                const float4 r0v = __ldg((const float4*)(W5 + i*NP));
                const float4 r1v = __ldg((const float4*)(W5 + i*NP + 4));
                g[0]=fmaf(x,r0v.x,g[0]); g[1]=fmaf(x,r0v.y,g[1]);
                g[2]=fmaf(x,r0v.z,g[2]); g[3]=fmaf(x,r0v.w,g[3]);
                g[4]=fmaf(x,r1v.x,g[4]); g[5]=fmaf(x,r1v.y,g[5]);
                g[6]=fmaf(x,r1v.z,g[6]); g[7]=fmaf(x,r1v.w,g[7]);
            }
            float res[NP];
            #pragma unroll
            for (int j = 1; j <= NP; j++) {
                float f = __ldg(b6 + j);
                #pragma unroll
                for (int i = 0; i < NP; i++)
                    f = fmaf(g[i], __ldg(W6 + i * IN_D + j), f);
                res[j-1] = s_in[row*12 + j] + f;
            }
            if (pos < k) {
                float4* op = (float4*)(out + (size_t)pos * NP);
                op[0] = make_float4(res[0], res[1], res[2], res[3]);
                op[1] = make_float4(res[4], res[5], res[6], res[7]);
            }
        }
    }
}

// ---------------- launch ----------------
extern "C" void kernel_launch(void* const* d_in, const int* in_sizes, int n_in,
                              void* d_out, int out_size)
{
    const float* data     = (const float*)d_in[0];
    const int*   elements = (const int*)  d_in[1];
    const float* W0 = (const float*)d_in[2];  const float* b0 = (const float*)d_in[3];
    const float* W1 = (const float*)d_in[4];  const float* b1 = (const float*)d_in[5];
    const float* W2 = (const float*)d_in[6];  const float* b2 = (const float*)d_in[7];
    const float* W3 = (const float*)d_in[8];  const float* b3 = (const float*)d_in[9];
    const float* W4 = (const float*)d_in[10]; const float* b4 = (const float*)d_in[11];
    const float* W5 = (const float*)d_in[12]; const float* b5 = (const float*)d_in[13];
    const float* W6 = (const float*)d_in[14]; const float* b6 = (const float*)d_in[15];
    float* out = (float*)d_out;

    const int k = in_sizes[1];

    prep_kernel<<<dim3(8, 4), 256>>>(W0, W1, W2, W3);

    const int grid = (k + TILE_M - 1) / TILE_M;
    const size_t smem = 143392u + 1024u;
    cudaFuncSetAttribute(ElementGNN_rc_kernel,
                         cudaFuncAttributeMaxDynamicSharedMemorySize, (int)smem);
    ElementGNN_rc_kernel<<<grid, THREADS, smem>>>(
        data, elements, b0, b1, b2, b3, W4, b4, W5, b5, W6, b6, out, k);
}

// round 5
// speedup vs baseline: 3.1428x; 1.1367x over previous
#include <cuda_runtime.h>
#include <cuda_bf16.h>
#include <stdint.h>

#define NP      8
#define NP1     9
#define IN_D    10
#define THREADS 128          // 4 compute warps; warp 0 lane 0 also drives copies
#define TILE_M  64

// Flat weight image, half-layer blocks:
//   L0 block   @ 0      : Wh 4KB | Wl 4KB                     (8KB)
//   block(l,h) @ 8192 + ((l-1)*2+h)*32768 : Wh 16KB | Wl 16KB (32KB), l=1..3, h=0..1
__device__ __align__(16) unsigned char g_W[204800];

// ---------------- helpers ----------------
__device__ __forceinline__ uint32_t smem_u32(const void* p){
    uint32_t a;
    asm("{ .reg .u64 t; cvta.to.shared.u64 t, %1; cvt.u32.u64 %0, t; }" : "=r"(a) : "l"(p));
    return a;
}
__device__ __forceinline__ uint32_t packbf(float x0, float x1){ // x0 -> low half
    uint32_t r; asm("cvt.rn.bf16x2.f32 %0, %1, %2;" : "=r"(r) : "f"(x1), "f"(x0)); return r;
}
__device__ __forceinline__ float bflo(uint32_t u){ return __uint_as_float(u<<16); }
__device__ __forceinline__ float bfhi(uint32_t u){ return __uint_as_float(u & 0xFFFF0000u); }

#define MBAR_INIT(a,c)   asm volatile("mbarrier.init.shared.b64 [%0], %1;" :: "r"(a), "r"(c) : "memory")
#define MBAR_EXPECT(a,b) asm volatile("mbarrier.arrive.expect_tx.shared.b64 _, [%0], %1;" :: "r"(a), "r"(b) : "memory")
#define MBAR_ARRIVE(a)   asm volatile("mbarrier.arrive.shared.b64 _, [%0];" :: "r"(a) : "memory")
#define FENCE_PROXY()    asm volatile("fence.proxy.async.shared::cta;" ::: "memory")

__device__ __forceinline__ void mbar_wait(uint32_t mbar, uint32_t parity){
    asm volatile(
        "{\n\t.reg .pred P;\n\t"
        "WL_%=:\n\t"
        "mbarrier.try_wait.parity.acquire.cta.shared::cta.b64 P, [%0], %1, 0x989680;\n\t"
        "@P bra.uni WD_%=;\n\t"
        "bra.uni WL_%=;\n\t"
        "WD_%=:\n\t}"
        :: "r"(mbar), "r"(parity) : "memory");
}
__device__ __forceinline__ void bulk_copy(uint32_t dst, const void* src, uint32_t bytes, uint32_t mbar){
    asm volatile(
        "cp.async.bulk.shared::cta.global.mbarrier::complete_tx::bytes [%0], [%1], %2, [%3];"
        :: "r"(dst), "l"(src), "r"(bytes), "r"(mbar) : "memory");
}

#define LDS128(r0,r1,r2,r3,addr) \
    asm volatile("ld.shared.v4.b32 {%0,%1,%2,%3}, [%4];" : "=r"(r0),"=r"(r1),"=r"(r2),"=r"(r3) : "r"(addr))

#define MMA_BF16(C, a0,a1,a2,a3, b0,b1) \
    asm volatile("mma.sync.aligned.m16n8k16.row.col.f32.bf16.bf16.f32 " \
        "{%0,%1,%2,%3}, {%4,%5,%6,%7}, {%8,%9}, {%0,%1,%2,%3};" \
        : "+f"((C)[0]), "+f"((C)[1]), "+f"((C)[2]), "+f"((C)[3]) \
        : "r"(a0), "r"(a1), "r"(a2), "r"(a3), "r"(b0), "r"(b1))

// ---------------- weight prep ----------------
__global__ void prep_kernel(const float* __restrict__ W0, const float* __restrict__ W1,
                            const float* __restrict__ W2, const float* __restrict__ W3)
{
    const int layer = blockIdx.y;
    const int idx   = blockIdx.x * 256 + threadIdx.x;   // (ks*8+ntp)*32+lane
    const int lane  = idx & 31;
    const int rest  = idx >> 5;
    const int ntp   = rest & 7;
    const int ks    = rest >> 3;                        // 0..7
    if (layer == 0 && ks > 0) return;

    const float* W = (layer == 0) ? W0 : (layer == 1) ? W1 : (layer == 2) ? W2 : W3;
    const int KMAX = (layer == 0) ? IN_D : 128;

    uint32_t hi[4], lo[4];
    #pragma unroll
    for (int h = 0; h < 2; h++) {
        const int n  = (2*ntp + h) * 8 + (lane >> 2);
        const int t  = lane & 3;
        const int kb = ks * 16;
        const int kr[4] = { kb + 2*t, kb + 2*t + 1, kb + 2*t + 8, kb + 2*t + 9 };
        float v[4], f[4];
        #pragma unroll
        for (int i = 0; i < 4; i++) {
            v[i] = (kr[i] < KMAX) ? __ldg(W + kr[i] * 128 + n) : 0.f;
            f[i] = __bfloat162float(__float2bfloat16(v[i]));
        }
        hi[2*h]   = packbf(f[0], f[1]);
        hi[2*h+1] = packbf(f[2], f[3]);
        lo[2*h]   = packbf(v[0]-f[0], v[1]-f[1]);
        lo[2*h+1] = packbf(v[2]-f[2], v[3]-f[3]);
    }

    size_t base, whOff, wlGap;
    if (layer == 0) {
        base  = 0;
        whOff = (size_t)(ntp * 32 + lane) * 16;
        wlGap = 4096;
    } else {
        const int half = ks >> 2, ksl = ks & 3;
        base  = 8192 + (size_t)((layer-1)*2 + half) * 32768;
        whOff = (size_t)((ksl*8 + ntp) * 32 + lane) * 16;
        wlGap = 16384;
    }
    *(uint4*)(&g_W[base + whOff])         = make_uint4(hi[0],hi[1],hi[2],hi[3]);
    *(uint4*)(&g_W[base + wlGap + whOff]) = make_uint4(lo[0],lo[1],lo[2],lo[3]);
}

// ---------------- half-layer MMA: 16-way independent ordering ----------------
template <int NKSL, int KSBASE>
__device__ __forceinline__ void run_half(float acc[16][4],
                                         const uint32_t aHi[8][4], const uint32_t aLo[8][4],
                                         uint32_t wbase, uint32_t wlGap, int lane)
{
    const uint32_t lof = (uint32_t)lane * 16u;
    #pragma unroll
    for (int ksl = 0; ksl < NKSL; ksl++) {
        const int ks = KSBASE + ksl;
        uint32_t w[8][4];
        #pragma unroll
        for (int ntp = 0; ntp < 8; ntp++)
            LDS128(w[ntp][0],w[ntp][1],w[ntp][2],w[ntp][3],
                   wbase + (uint32_t)((ksl*8 + ntp)*32)*16u + lof);
        #pragma unroll
        for (int ntp = 0; ntp < 8; ntp++) {           // 16 independent: Ah x Wh
            MMA_BF16(acc[2*ntp],   aHi[ks][0],aHi[ks][1],aHi[ks][2],aHi[ks][3], w[ntp][0],w[ntp][1]);
            MMA_BF16(acc[2*ntp+1], aHi[ks][0],aHi[ks][1],aHi[ks][2],aHi[ks][3], w[ntp][2],w[ntp][3]);
        }
        #pragma unroll
        for (int ntp = 0; ntp < 8; ntp++) {           // 16 independent: Al x Wh (reuse regs)
            MMA_BF16(acc[2*ntp],   aLo[ks][0],aLo[ks][1],aLo[ks][2],aLo[ks][3], w[ntp][0],w[ntp][1]);
            MMA_BF16(acc[2*ntp+1], aLo[ks][0],aLo[ks][1],aLo[ks][2],aLo[ks][3], w[ntp][2],w[ntp][3]);
        }
        #pragma unroll
        for (int ntp = 0; ntp < 8; ntp++)
            LDS128(w[ntp][0],w[ntp][1],w[ntp][2],w[ntp][3],
                   wbase + wlGap + (uint32_t)((ksl*8 + ntp)*32)*16u + lof);
        #pragma unroll
        for (int ntp = 0; ntp < 8; ntp++) {           // 16 independent: Ah x Wl
            MMA_BF16(acc[2*ntp],   aHi[ks][0],aHi[ks][1],aHi[ks][2],aHi[ks][3], w[ntp][0],w[ntp][1]);
            MMA_BF16(acc[2*ntp+1], aHi[ks][0],aHi[ks][1],aHi[ks][2],aHi[ks][3], w[ntp][2],w[ntp][3]);
        }
    }
}

// D frags + bias (+relu) -> next layer A frags (registers); zeroes acc.
template <bool RELU>
__device__ __forceinline__ void make_A(float acc[16][4],
                                       uint32_t aHi[8][4], uint32_t aLo[8][4],
                                       const float* __restrict__ biasL, int c)
{
    #pragma unroll
    for (int kt = 0; kt < 8; kt++) {
        #pragma unroll
        for (int h = 0; h < 2; h++) {
            const int nt = 2*kt + h;
            const float b0 = biasL[nt*8 + 2*c];
            const float b1 = biasL[nt*8 + 2*c + 1];
            float x0 = acc[nt][0] + b0, x1 = acc[nt][1] + b1;
            float x2 = acc[nt][2] + b0, x3 = acc[nt][3] + b1;
            if (RELU) {
                x0 = fmaxf(x0,0.f); x1 = fmaxf(x1,0.f);
                x2 = fmaxf(x2,0.f); x3 = fmaxf(x3,0.f);
            }
            const uint32_t H0 = packbf(x0,x1), H1 = packbf(x2,x3);
            aHi[kt][2*h]   = H0;  aLo[kt][2*h]   = packbf(x0-bflo(H0), x1-bfhi(H0));
            aHi[kt][2*h+1] = H1;  aLo[kt][2*h+1] = packbf(x2-bflo(H1), x3-bfhi(H1));
            acc[nt][0]=0.f; acc[nt][1]=0.f; acc[nt][2]=0.f; acc[nt][3]=0.f;
        }
    }
}

// ---------------- main kernel ----------------
__global__ void __launch_bounds__(THREADS, 2)
ElementGNN_rc2_kernel(const float* __restrict__ data,
                      const int*   __restrict__ elements,
                      const float* __restrict__ b0, const float* __restrict__ b1,
                      const float* __restrict__ b2, const float* __restrict__ b3,
                      const float* __restrict__ W4, const float* __restrict__ b4,
                      const float* __restrict__ W5, const float* __restrict__ b5,
                      const float* __restrict__ W6, const float* __restrict__ b6,
                      float* __restrict__ out, int k)
{
    extern __shared__ char smraw[];
    const uint32_t raw = smem_u32(smraw);
    const uint32_t s0  = (raw + 1023u) & ~1023u;
    char* base = smraw + (s0 - raw);

    const uint32_t wBuf0 = s0;                 // 32KB
    const uint32_t wBuf1 = s0 + 32768u;        // 32KB
    float* s_in  = (float*)(base + 65536);     // [64][12] fp32 (3072B)
    float* sBias = (float*)(base + 68608);     // [4][128]      (2048B)
    float* sW4   = (float*)(base + 70656);     // [128][8]      (4096B)
    const uint32_t full0  = s0 + 74752u;
    const uint32_t full1  = s0 + 74760u;
    const uint32_t empty0 = s0 + 74768u;
    const uint32_t empty1 = s0 + 74776u;

    const int tid  = threadIdx.x;
    const int warp = tid >> 5;
    const int lane = tid & 31;
    const int basE = blockIdx.x * TILE_M;

    if (tid == 0) {
        MBAR_INIT(full0, 1);  MBAR_INIT(full1, 1);
        MBAR_INIT(empty0, 4); MBAR_INIT(empty1, 4);
        FENCE_PROXY();
    }
    __syncthreads();
    if (tid == 0) {
        MBAR_EXPECT(full0, 8192u);  bulk_copy(wBuf0, &g_W[0],    8192u,  full0);  // L0
        MBAR_EXPECT(full1, 32768u); bulk_copy(wBuf1, &g_W[8192], 32768u, full1);  // L1a
    }

    // ---- gather (64 rows) + bias + W4 staging ----
    if (tid < TILE_M) {
        const int m = tid, pos = basE + m;
        float v[IN_D];
        #pragma unroll
        for (int j = 0; j < IN_D; j++) v[j] = 0.f;
        if (pos < k) {
            const int e  = elements[pos] / NP1;
            const int le = (e == 0) ? (k - 1) : (e - 1);
            const int ri = (e == k - 1) ? 0 : (e + 1);
            const float4 a0 = __ldg((const float4*)(data + (size_t)e * NP));
            const float4 a1 = __ldg((const float4*)(data + (size_t)e * NP + 4));
            v[0] = __ldg(data + (size_t)le * NP + (NP - 1));
            v[1]=a0.x; v[2]=a0.y; v[3]=a0.z; v[4]=a0.w;
            v[5]=a1.x; v[6]=a1.y; v[7]=a1.z; v[8]=a1.w;
            v[9] = __ldg(data + (size_t)ri * NP);
        }
        #pragma unroll
        for (int j = 0; j < IN_D; j++) s_in[m*12 + j] = v[j];
    }
    if (tid < 128) {
        sBias[0*128 + tid] = __ldg(b0 + tid);
        sBias[1*128 + tid] = __ldg(b1 + tid);
        sBias[2*128 + tid] = __ldg(b2 + tid);
        sBias[3*128 + tid] = __ldg(b3 + tid);
    }
    #pragma unroll
    for (int i = tid; i < 128*NP; i += THREADS) sW4[i] = __ldg(W4 + i);
    __syncthreads();

    // ---- per-warp layer-0 A frags ----
    const int gr = lane >> 2, c = lane & 3;
    const int r0 = warp * 16 + gr;            // rows r0, r0+8 (local 0..63)

    uint32_t aHi[8][4], aLo[8][4];
    {
        const int cols[4] = { 2*c, 2*c+1, 2*c+8, 2*c+9 };
        float f0[4], f1[4];
        #pragma unroll
        for (int i = 0; i < 4; i++) {
            f0[i] = (cols[i] < IN_D) ? s_in[r0*12 + cols[i]]     : 0.f;
            f1[i] = (cols[i] < IN_D) ? s_in[(r0+8)*12 + cols[i]] : 0.f;
        }
        const uint32_t H0 = packbf(f0[0], f0[1]), H1 = packbf(f1[0], f1[1]);
        const uint32_t H2 = packbf(f0[2], f0[3]), H3 = packbf(f1[2], f1[3]);
        aHi[0][0]=H0; aLo[0][0]=packbf(f0[0]-bflo(H0), f0[1]-bfhi(H0));
        aHi[0][1]=H1; aLo[0][1]=packbf(f1[0]-bflo(H1), f1[1]-bfhi(H1));
        aHi[0][2]=H2; aLo[0][2]=packbf(f0[2]-bflo(H2), f0[3]-bfhi(H2));
        aHi[0][3]=H3; aLo[0][3]=packbf(f1[2]-bflo(H3), f1[3]-bfhi(H3));
    }

    float acc[16][4];
    #pragma unroll
    for (int i = 0; i < 16; i++) { acc[i][0]=0.f; acc[i][1]=0.f; acc[i][2]=0.f; acc[i][3]=0.f; }

    const bool prod = (warp == 0 && lane == 0);

    // L0 : buf0 @ p0
    mbar_wait(full0, 0);
    run_half<1,0>(acc, aHi, aLo, wBuf0, 4096u, lane);
    __syncwarp(); if (lane == 0) MBAR_ARRIVE(empty0);
    if (prod) { mbar_wait(empty0, 0);
        MBAR_EXPECT(full0, 32768u); bulk_copy(wBuf0, &g_W[8192 + 1*32768], 32768u, full0); } // L1b
    make_A<true>(acc, aHi, aLo, sBias + 0*128, c);

    // L1a : buf1 @ p0
    mbar_wait(full1, 0);
    run_half<4,0>(acc, aHi, aLo, wBuf1, 16384u, lane);
    __syncwarp(); if (lane == 0) MBAR_ARRIVE(empty1);
    if (prod) { mbar_wait(empty1, 0);
        MBAR_EXPECT(full1, 32768u); bulk_copy(wBuf1, &g_W[8192 + 2*32768], 32768u, full1); } // L2a

    // L1b : buf0 @ p1
    mbar_wait(full0, 1);
    run_half<4,4>(acc, aHi, aLo, wBuf0, 16384u, lane);
    __syncwarp(); if (lane == 0) MBAR_ARRIVE(empty0);
    if (prod) { mbar_wait(empty0, 1);
        MBAR_EXPECT(full0, 32768u); bulk_copy(wBuf0, &g_W[8192 + 3*32768], 32768u, full0); } // L2b
    make_A<false>(acc, aHi, aLo, sBias + 1*128, c);

    // L2a : buf1 @ p1
    mbar_wait(full1, 1);
    run_half<4,0>(acc, aHi, aLo, wBuf1, 16384u, lane);
    __syncwarp(); if (lane == 0) MBAR_ARRIVE(empty1);
    if (prod) { mbar_wait(empty1, 1);
        MBAR_EXPECT(full1, 32768u); bulk_copy(wBuf1, &g_W[8192 + 4*32768], 32768u, full1); } // L3a

    // L2b : buf0 @ p0
    mbar_wait(full0, 0);
    run_half<4,4>(acc, aHi, aLo, wBuf0, 16384u, lane);
    __syncwarp(); if (lane == 0) MBAR_ARRIVE(empty0);
    if (prod) { mbar_wait(empty0, 0);
        MBAR_EXPECT(full0, 32768u); bulk_copy(wBuf0, &g_W[8192 + 5*32768], 32768u, full0); } // L3b
    make_A<true>(acc, aHi, aLo, sBias + 2*128, c);

    // L3a : buf1 @ p0
    mbar_wait(full1, 0);
    run_half<4,0>(acc, aHi, aLo, wBuf1, 16384u, lane);

    // L3b : buf0 @ p1
    mbar_wait(full0, 1);
    run_half<4,4>(acc, aHi, aLo, wBuf0, 16384u, lane);

    // ---- tail: bias3 + GEMV 128->8, quad reduce, scalar finish ----
    float h0[NP], h1[NP];
    #pragma unroll
    for (int j = 0; j < NP; j++) { h0[j]=0.f; h1[j]=0.f; }
    const float* bias3 = sBias + 3*128;
    #pragma unroll
    for (int nt = 0; nt < 16; nt++) {
        const float bb0 = bias3[nt*8 + 2*c], bb1 = bias3[nt*8 + 2*c + 1];
        const float xa = acc[nt][0]+bb0, xb = acc[nt][1]+bb1;
        const float xc = acc[nt][2]+bb0, xd = acc[nt][3]+bb1;
        const int col0 = nt*8 + 2*c;
        const float4 wA0 = *(const float4*)(sW4 + col0*NP);
        const float4 wA1 = *(const float4*)(sW4 + col0*NP + 4);
        const float4 wB0 = *(const float4*)(sW4 + (col0+1)*NP);
        const float4 wB1 = *(const float4*)(sW4 + (col0+1)*NP + 4);
        h0[0]=fmaf(xa,wA0.x,fmaf(xb,wB0.x,h0[0])); h0[1]=fmaf(xa,wA0.y,fmaf(xb,wB0.y,h0[1]));
        h0[2]=fmaf(xa,wA0.z,fmaf(xb,wB0.z,h0[2])); h0[3]=fmaf(xa,wA0.w,fmaf(xb,wB0.w,h0[3]));
        h0[4]=fmaf(xa,wA1.x,fmaf(xb,wB1.x,h0[4])); h0[5]=fmaf(xa,wA1.y,fmaf(xb,wB1.y,h0[5]));
        h0[6]=fmaf(xa,wA1.z,fmaf(xb,wB1.z,h0[6])); h0[7]=fmaf(xa,wA1.w,fmaf(xb,wB1.w,h0[7]));
        h1[0]=fmaf(xc,wA0.x,fmaf(xd,wB0.x,h1[0])); h1[1]=fmaf(xc,wA0.y,fmaf(xd,wB0.y,h1[1]));
        h1[2]=fmaf(xc,wA0.z,fmaf(xd,wB0.z,h1[2])); h1[3]=fmaf(xc,wA0.w,fmaf(xd,wB0.w,h1[3]));
        h1[4]=fmaf(xc,wA1.x,fmaf(xd,wB1.x,h1[4])); h1[5]=fmaf(xc,wA1.y,fmaf(xd,wB1.y,h1[5]));
        h1[6]=fmaf(xc,wA1.z,fmaf(xd,wB1.z,h1[6])); h1[7]=fmaf(xc,wA1.w,fmaf(xd,wB1.w,h1[7]));
    }
    #pragma unroll
    for (int j = 0; j < NP; j++) {
        h0[j] += __shfl_xor_sync(0xffffffffu, h0[j], 1);
        h0[j] += __shfl_xor_sync(0xffffffffu, h0[j], 2);
        h1[j] += __shfl_xor_sync(0xffffffffu, h1[j], 1);
        h1[j] += __shfl_xor_sync(0xffffffffu, h1[j], 2);
    }

    if (c == 0) {
        #pragma unroll
        for (int half = 0; half < 2; half++) {
            const float* hh = half ? h1 : h0;
            const int row = r0 + half * 8;
            const int pos = basE + row;

            float hv[NP];
            {
                const float4 q0 = __ldg((const float4*)(b4));
                const float4 q1 = __ldg((const float4*)(b4 + 4));
                hv[0]=fmaxf(hh[0]+q0.x,0.f); hv[1]=fmaxf(hh[1]+q0.y,0.f);
                hv[2]=fmaxf(hh[2]+q0.z,0.f); hv[3]=fmaxf(hh[3]+q0.w,0.f);
                hv[4]=fmaxf(hh[4]+q1.x,0.f); hv[5]=fmaxf(hh[5]+q1.y,0.f);
                hv[6]=fmaxf(hh[6]+q1.z,0.f); hv[7]=fmaxf(hh[7]+q1.w,0.f);
            }
            float g[NP];
            {
                const float4 q0 = __ldg((const float4*)(b5));
                const float4 q1 = __ldg((const float4*)(b5 + 4));
                g[0]=q0.x; g[1]=q0.y; g[2]=q0.z; g[3]=q0.w;
                g[4]=q1.x; g[5]=q1.y; g[6]=q1.z; g[7]=q1.w;
            }
            #pragma unroll
            for (int i = 0; i < NP; i++) {
                const float x = hv[i];
                const float4 r0v = __ldg((const float4*)(W5 + i*NP));
                const float4 r1v = __ldg((const float4*)(W5 + i*NP + 4));
                g[0]=fmaf(x,r0v.x,g[0]); g[1]=fmaf(x,r0v.y,g[1]);
                g[2]=fmaf(x,r0v.z,g[2]); g[3]=fmaf(x,r0v.w,g[3]);
                g[4]=fmaf(x,r1v.x,g[4]); g[5]=fmaf(x,r1v.y,g[5]);
                g[6]=fmaf(x,r1v.z,g[6]); g[7]=fmaf(x,r1v.w,g[7]);
            }
            float res[NP];
            #pragma unroll
            for (int j = 1; j <= NP; j++) {
                float f = __ldg(b6 + j);
                #pragma unroll
                for (int i = 0; i < NP; i++)
                    f = fmaf(g[i], __ldg(W6 + i * IN_D + j), f);
                res[j-1] = s_in[row*12 + j] + f;
            }
            if (pos < k) {
                float4* op = (float4*)(out + (size_t)pos * NP);
                op[0] = make_float4(res[0], res[1], res[2], res[3]);
                op[1] = make_float4(res[4], res[5], res[6], res[7]);
            }
        }
    }
}

// ---------------- launch ----------------
extern "C" void kernel_launch(void* const* d_in, const int* in_sizes, int n_in,
                              void* d_out, int out_size)
{
    const float* data     = (const float*)d_in[0];
    const int*   elements = (const int*)  d_in[1];
    const float* W0 = (const float*)d_in[2];  const float* b0 = (const float*)d_in[3];
    const float* W1 = (const float*)d_in[4];  const float* b1 = (const float*)d_in[5];
    const float* W2 = (const float*)d_in[6];  const float* b2 = (const float*)d_in[7];
    const float* W3 = (const float*)d_in[8];  const float* b3 = (const float*)d_in[9];
    const float* W4 = (const float*)d_in[10]; const float* b4 = (const float*)d_in[11];
    const float* W5 = (const float*)d_in[12]; const float* b5 = (const float*)d_in[13];
    const float* W6 = (const float*)d_in[14]; const float* b6 = (const float*)d_in[15];
    float* out = (float*)d_out;

    const int k = in_sizes[1];

    prep_kernel<<<dim3(8, 4), 256>>>(W0, W1, W2, W3);

    const int grid = (k + TILE_M - 1) / TILE_M;
    const size_t smem = 74784u + 1024u;
    cudaFuncSetAttribute(ElementGNN_rc2_kernel,
                         cudaFuncAttributeMaxDynamicSharedMemorySize, (int)smem);
    ElementGNN_rc2_kernel<<<grid, THREADS, smem>>>(
        data, elements, b0, b1, b2, b3, W4, b4, W5, b5, W6, b6, out, k);
}

// round 6
// speedup vs baseline: 4.4285x; 1.4091x over previous
#include <cuda_runtime.h>
#include <cuda_fp16.h>
#include <stdint.h>

#define NP      8
#define NP1     9
#define IN_D    10
#define THREADS 128          // 4 compute warps, m32 each; warp 0 lane 0 drives copies
#define TILE_M  128

// Flat weight image, half-layer blocks (fp16 hi/lo):
//   L0 block   @ 0      : Wh 4KB | Wl 4KB                     (8KB)
//   block(l,h) @ 8192 + ((l-1)*2+h)*32768 : Wh 16KB | Wl 16KB (32KB), l=1..3, h=0..1
__device__ __align__(16) unsigned char g_W[204800];

// ---------------- helpers ----------------
__device__ __forceinline__ uint32_t smem_u32(const void* p){
    uint32_t a;
    asm("{ .reg .u64 t; cvta.to.shared.u64 t, %1; cvt.u32.u64 %0, t; }" : "=r"(a) : "l"(p));
    return a;
}
__device__ __forceinline__ uint32_t packf16(float x0, float x1){ // x0 -> low half
    uint32_t r; asm("cvt.rn.f16x2.f32 %0, %1, %2;" : "=r"(r) : "f"(x1), "f"(x0)); return r;
}

#define MBAR_INIT(a,c)   asm volatile("mbarrier.init.shared.b64 [%0], %1;" :: "r"(a), "r"(c) : "memory")
#define MBAR_EXPECT(a,b) asm volatile("mbarrier.arrive.expect_tx.shared.b64 _, [%0], %1;" :: "r"(a), "r"(b) : "memory")
#define MBAR_ARRIVE(a)   asm volatile("mbarrier.arrive.shared.b64 _, [%0];" :: "r"(a) : "memory")
#define FENCE_PROXY()    asm volatile("fence.proxy.async.shared::cta;" ::: "memory")

__device__ __forceinline__ void mbar_wait(uint32_t mbar, uint32_t parity){
    asm volatile(
        "{\n\t.reg .pred P;\n\t"
        "WL_%=:\n\t"
        "mbarrier.try_wait.parity.acquire.cta.shared::cta.b64 P, [%0], %1, 0x989680;\n\t"
        "@P bra.uni WD_%=;\n\t"
        "bra.uni WL_%=;\n\t"
        "WD_%=:\n\t}"
        :: "r"(mbar), "r"(parity) : "memory");
}
__device__ __forceinline__ void bulk_copy(uint32_t dst, const void* src, uint32_t bytes, uint32_t mbar){
    asm volatile(
        "cp.async.bulk.shared::cta.global.mbarrier::complete_tx::bytes [%0], [%1], %2, [%3];"
        :: "r"(dst), "l"(src), "r"(bytes), "r"(mbar) : "memory");
}

#define LDS128(r0,r1,r2,r3,addr) \
    asm volatile("ld.shared.v4.b32 {%0,%1,%2,%3}, [%4];" : "=r"(r0),"=r"(r1),"=r"(r2),"=r"(r3) : "r"(addr))

#define MMA_F16(C, a0,a1,a2,a3, b0,b1) \
    asm volatile("mma.sync.aligned.m16n8k16.row.col.f32.f16.f16.f32 " \
        "{%0,%1,%2,%3}, {%4,%5,%6,%7}, {%8,%9}, {%0,%1,%2,%3};" \
        : "+f"((C)[0]), "+f"((C)[1]), "+f"((C)[2]), "+f"((C)[3]) \
        : "r"(a0), "r"(a1), "r"(a2), "r"(a3), "r"(b0), "r"(b1))

// ---------------- weight prep (fp16 hi/lo split) ----------------
__global__ void prep_kernel(const float* __restrict__ W0, const float* __restrict__ W1,
                            const float* __restrict__ W2, const float* __restrict__ W3)
{
    const int layer = blockIdx.y;
    const int idx   = blockIdx.x * 256 + threadIdx.x;   // (ks*8+ntp)*32+lane
    const int lane  = idx & 31;
    const int rest  = idx >> 5;
    const int ntp   = rest & 7;
    const int ks    = rest >> 3;                        // 0..7
    if (layer == 0 && ks > 0) return;

    const float* W = (layer == 0) ? W0 : (layer == 1) ? W1 : (layer == 2) ? W2 : W3;
    const int KMAX = (layer == 0) ? IN_D : 128;

    uint32_t hi[4], lo[4];
    #pragma unroll
    for (int h = 0; h < 2; h++) {
        const int n  = (2*ntp + h) * 8 + (lane >> 2);
        const int t  = lane & 3;
        const int kb = ks * 16;
        const int kr[4] = { kb + 2*t, kb + 2*t + 1, kb + 2*t + 8, kb + 2*t + 9 };
        float v[4], f[4];
        #pragma unroll
        for (int i = 0; i < 4; i++) {
            v[i] = (kr[i] < KMAX) ? __ldg(W + kr[i] * 128 + n) : 0.f;
            f[i] = __half2float(__float2half_rn(v[i]));
        }
        hi[2*h]   = packf16(f[0], f[1]);
        hi[2*h+1] = packf16(f[2], f[3]);
        lo[2*h]   = packf16(v[0]-f[0], v[1]-f[1]);
        lo[2*h+1] = packf16(v[2]-f[2], v[3]-f[3]);
    }

    size_t base, whOff, wlGap;
    if (layer == 0) {
        base  = 0;
        whOff = (size_t)(ntp * 32 + lane) * 16;
        wlGap = 4096;
    } else {
        const int half = ks >> 2, ksl = ks & 3;
        base  = 8192 + (size_t)((layer-1)*2 + half) * 32768;
        whOff = (size_t)((ksl*8 + ntp) * 32 + lane) * 16;
        wlGap = 16384;
    }
    *(uint4*)(&g_W[base + whOff])         = make_uint4(hi[0],hi[1],hi[2],hi[3]);
    *(uint4*)(&g_W[base + wlGap + whOff]) = make_uint4(lo[0],lo[1],lo[2],lo[3]);
}

// ---------------- half-layer MMA: m32, 2-pass (Wh, Wl), 32-deep independence ----------------
template <int NKSL, int KSBASE>
__device__ __forceinline__ void run_half(float acc[2][16][4],
                                         const uint32_t aH[2][8][4],
                                         uint32_t wbase, uint32_t wlGap, int lane)
{
    const uint32_t lof = (uint32_t)lane * 16u;
    #pragma unroll
    for (int ksl = 0; ksl < NKSL; ksl++) {
        const int ks = KSBASE + ksl;
        uint32_t w[8][4];
        #pragma unroll
        for (int ntp = 0; ntp < 8; ntp++)
            LDS128(w[ntp][0],w[ntp][1],w[ntp][2],w[ntp][3],
                   wbase + (uint32_t)((ksl*8 + ntp)*32)*16u + lof);
        #pragma unroll
        for (int ntp = 0; ntp < 8; ntp++) {
            #pragma unroll
            for (int mt = 0; mt < 2; mt++) {
                MMA_F16(acc[mt][2*ntp],   aH[mt][ks][0],aH[mt][ks][1],aH[mt][ks][2],aH[mt][ks][3], w[ntp][0],w[ntp][1]);
                MMA_F16(acc[mt][2*ntp+1], aH[mt][ks][0],aH[mt][ks][1],aH[mt][ks][2],aH[mt][ks][3], w[ntp][2],w[ntp][3]);
            }
        }
        #pragma unroll
        for (int ntp = 0; ntp < 8; ntp++)
            LDS128(w[ntp][0],w[ntp][1],w[ntp][2],w[ntp][3],
                   wbase + wlGap + (uint32_t)((ksl*8 + ntp)*32)*16u + lof);
        #pragma unroll
        for (int ntp = 0; ntp < 8; ntp++) {
            #pragma unroll
            for (int mt = 0; mt < 2; mt++) {
                MMA_F16(acc[mt][2*ntp],   aH[mt][ks][0],aH[mt][ks][1],aH[mt][ks][2],aH[mt][ks][3], w[ntp][0],w[ntp][1]);
                MMA_F16(acc[mt][2*ntp+1], aH[mt][ks][0],aH[mt][ks][1],aH[mt][ks][2],aH[mt][ks][3], w[ntp][2],w[ntp][3]);
            }
        }
    }
}

// D frags + bias (+relu) -> next layer A frags (fp16, single plane); zeroes acc.
template <bool RELU>
__device__ __forceinline__ void make_A(float acc[2][16][4], uint32_t aH[2][8][4],
                                       const float* __restrict__ biasL, int c)
{
    #pragma unroll
    for (int mt = 0; mt < 2; mt++) {
        #pragma unroll
        for (int kt = 0; kt < 8; kt++) {
            #pragma unroll
            for (int h = 0; h < 2; h++) {
                const int nt = 2*kt + h;
                const float b0 = biasL[nt*8 + 2*c];
                const float b1 = biasL[nt*8 + 2*c + 1];
                float x0 = acc[mt][nt][0] + b0, x1 = acc[mt][nt][1] + b1;
                float x2 = acc[mt][nt][2] + b0, x3 = acc[mt][nt][3] + b1;
                if (RELU) {
                    x0 = fmaxf(x0,0.f); x1 = fmaxf(x1,0.f);
                    x2 = fmaxf(x2,0.f); x3 = fmaxf(x3,0.f);
                }
                aH[mt][kt][2*h]   = packf16(x0, x1);
                aH[mt][kt][2*h+1] = packf16(x2, x3);
                acc[mt][nt][0]=0.f; acc[mt][nt][1]=0.f; acc[mt][nt][2]=0.f; acc[mt][nt][3]=0.f;
            }
        }
    }
}

// ---------------- main kernel ----------------
__global__ void __launch_bounds__(THREADS, 2)
ElementGNN_h2_kernel(const float* __restrict__ data,
                     const int*   __restrict__ elements,
                     const float* __restrict__ b0, const float* __restrict__ b1,
                     const float* __restrict__ b2, const float* __restrict__ b3,
                     const float* __restrict__ W4, const float* __restrict__ b4,
                     const float* __restrict__ W5, const float* __restrict__ b5,
                     const float* __restrict__ W6, const float* __restrict__ b6,
                     float* __restrict__ out, int k)
{
    extern __shared__ char smraw[];
    const uint32_t raw = smem_u32(smraw);
    const uint32_t s0  = (raw + 1023u) & ~1023u;
    char* base = smraw + (s0 - raw);

    const uint32_t wBuf0 = s0;                 // 32KB
    const uint32_t wBuf1 = s0 + 32768u;        // 32KB
    float* s_in  = (float*)(base + 65536);     // [128][12] fp32 (6144B)
    float* sBias = (float*)(base + 71680);     // [4][128]      (2048B)
    float* sW4   = (float*)(base + 73728);     // [128][8]      (4096B)
    const uint32_t full0  = s0 + 77824u;
    const uint32_t full1  = s0 + 77832u;
    const uint32_t empty0 = s0 + 77840u;
    const uint32_t empty1 = s0 + 77848u;

    const int tid  = threadIdx.x;
    const int warp = tid >> 5;
    const int lane = tid & 31;
    const int basE = blockIdx.x * TILE_M;

    if (tid == 0) {
        MBAR_INIT(full0, 1);  MBAR_INIT(full1, 1);
        MBAR_INIT(empty0, 4); MBAR_INIT(empty1, 4);
        FENCE_PROXY();
    }
    __syncthreads();
    if (tid == 0) {
        MBAR_EXPECT(full0, 8192u);  bulk_copy(wBuf0, &g_W[0],    8192u,  full0);  // L0
        MBAR_EXPECT(full1, 32768u); bulk_copy(wBuf1, &g_W[8192], 32768u, full1);  // L1a
    }

    // ---- gather (128 rows) + bias + W4 staging ----
    {
        const int m = tid, pos = basE + m;
        float v[IN_D];
        #pragma unroll
        for (int j = 0; j < IN_D; j++) v[j] = 0.f;
        if (pos < k) {
            const int e  = elements[pos] / NP1;
            const int le = (e == 0) ? (k - 1) : (e - 1);
            const int ri = (e == k - 1) ? 0 : (e + 1);
            const float4 a0 = __ldg((const float4*)(data + (size_t)e * NP));
            const float4 a1 = __ldg((const float4*)(data + (size_t)e * NP + 4));
            v[0] = __ldg(data + (size_t)le * NP + (NP - 1));
            v[1]=a0.x; v[2]=a0.y; v[3]=a0.z; v[4]=a0.w;
            v[5]=a1.x; v[6]=a1.y; v[7]=a1.z; v[8]=a1.w;
            v[9] = __ldg(data + (size_t)ri * NP);
        }
        #pragma unroll
        for (int j = 0; j < IN_D; j++) s_in[m*12 + j] = v[j];
        sBias[0*128 + m] = __ldg(b0 + m);
        sBias[1*128 + m] = __ldg(b1 + m);
        sBias[2*128 + m] = __ldg(b2 + m);
        sBias[3*128 + m] = __ldg(b3 + m);
        #pragma unroll
        for (int i = m; i < 128*NP; i += THREADS) sW4[i] = __ldg(W4 + i);
    }
    __syncthreads();

    // ---- per-warp layer-0 A frags (m32 = 2 m16 tiles) ----
    const int gr = lane >> 2, c = lane & 3;

    uint32_t aH[2][8][4];
    #pragma unroll
    for (int mt = 0; mt < 2; mt++) {
        const int r0 = warp * 32 + mt * 16 + gr;   // rows r0, r0+8
        const int cols[4] = { 2*c, 2*c+1, 2*c+8, 2*c+9 };
        float f0[4], f1[4];
        #pragma unroll
        for (int i = 0; i < 4; i++) {
            f0[i] = (cols[i] < IN_D) ? s_in[r0*12 + cols[i]]     : 0.f;
            f1[i] = (cols[i] < IN_D) ? s_in[(r0+8)*12 + cols[i]] : 0.f;
        }
        aH[mt][0][0] = packf16(f0[0], f0[1]);
        aH[mt][0][1] = packf16(f1[0], f1[1]);
        aH[mt][0][2] = packf16(f0[2], f0[3]);
        aH[mt][0][3] = packf16(f1[2], f1[3]);
    }

    float acc[2][16][4];
    #pragma unroll
    for (int mt = 0; mt < 2; mt++)
        #pragma unroll
        for (int i = 0; i < 16; i++) {
            acc[mt][i][0]=0.f; acc[mt][i][1]=0.f; acc[mt][i][2]=0.f; acc[mt][i][3]=0.f;
        }

    const bool prod = (warp == 0 && lane == 0);

    // L0 : buf0 @ p0
    mbar_wait(full0, 0);
    run_half<1,0>(acc, aH, wBuf0, 4096u, lane);
    __syncwarp(); if (lane == 0) MBAR_ARRIVE(empty0);
    if (prod) { mbar_wait(empty0, 0);
        MBAR_EXPECT(full0, 32768u); bulk_copy(wBuf0, &g_W[8192 + 1*32768], 32768u, full0); } // L1b
    make_A<true>(acc, aH, sBias + 0*128, c);

    // L1a : buf1 @ p0
    mbar_wait(full1, 0);
    run_half<4,0>(acc, aH, wBuf1, 16384u, lane);
    __syncwarp(); if (lane == 0) MBAR_ARRIVE(empty1);
    if (prod) { mbar_wait(empty1, 0);
        MBAR_EXPECT(full1, 32768u); bulk_copy(wBuf1, &g_W[8192 + 2*32768], 32768u, full1); } // L2a

    // L1b : buf0 @ p1
    mbar_wait(full0, 1);
    run_half<4,4>(acc, aH, wBuf0, 16384u, lane);
    __syncwarp(); if (lane == 0) MBAR_ARRIVE(empty0);
    if (prod) { mbar_wait(empty0, 1);
        MBAR_EXPECT(full0, 32768u); bulk_copy(wBuf0, &g_W[8192 + 3*32768], 32768u, full0); } // L2b
    make_A<false>(acc, aH, sBias + 1*128, c);

    // L2a : buf1 @ p1
    mbar_wait(full1, 1);
    run_half<4,0>(acc, aH, wBuf1, 16384u, lane);
    __syncwarp(); if (lane == 0) MBAR_ARRIVE(empty1);
    if (prod) { mbar_wait(empty1, 1);
        MBAR_EXPECT(full1, 32768u); bulk_copy(wBuf1, &g_W[8192 + 4*32768], 32768u, full1); } // L3a

    // L2b : buf0 @ p0
    mbar_wait(full0, 0);
    run_half<4,4>(acc, aH, wBuf0, 16384u, lane);
    __syncwarp(); if (lane == 0) MBAR_ARRIVE(empty0);
    if (prod) { mbar_wait(empty0, 0);
        MBAR_EXPECT(full0, 32768u); bulk_copy(wBuf0, &g_W[8192 + 5*32768], 32768u, full0); } // L3b
    make_A<true>(acc, aH, sBias + 2*128, c);

    // L3a : buf1 @ p0
    mbar_wait(full1, 0);
    run_half<4,0>(acc, aH, wBuf1, 16384u, lane);

    // L3b : buf0 @ p1
    mbar_wait(full0, 1);
    run_half<4,4>(acc, aH, wBuf0, 16384u, lane);

    // ---- tail per m16 tile: bias3 + GEMV 128->8, quad reduce, scalar finish ----
    const float* bias3 = sBias + 3*128;
    #pragma unroll
    for (int mt = 0; mt < 2; mt++) {
        float h0[NP], h1[NP];
        #pragma unroll
        for (int j = 0; j < NP; j++) { h0[j]=0.f; h1[j]=0.f; }
        #pragma unroll
        for (int nt = 0; nt < 16; nt++) {
            const float bb0 = bias3[nt*8 + 2*c], bb1 = bias3[nt*8 + 2*c + 1];
            const float xa = acc[mt][nt][0]+bb0, xb = acc[mt][nt][1]+bb1;
            const float xc = acc[mt][nt][2]+bb0, xd = acc[mt][nt][3]+bb1;
            const int col0 = nt*8 + 2*c;
            const float4 wA0 = *(const float4*)(sW4 + col0*NP);
            const float4 wA1 = *(const float4*)(sW4 + col0*NP + 4);
            const float4 wB0 = *(const float4*)(sW4 + (col0+1)*NP);
            const float4 wB1 = *(const float4*)(sW4 + (col0+1)*NP + 4);
            h0[0]=fmaf(xa,wA0.x,fmaf(xb,wB0.x,h0[0])); h0[1]=fmaf(xa,wA0.y,fmaf(xb,wB0.y,h0[1]));
            h0[2]=fmaf(xa,wA0.z,fmaf(xb,wB0.z,h0[2])); h0[3]=fmaf(xa,wA0.w,fmaf(xb,wB0.w,h0[3]));
            h0[4]=fmaf(xa,wA1.x,fmaf(xb,wB1.x,h0[4])); h0[5]=fmaf(xa,wA1.y,fmaf(xb,wB1.y,h0[5]));
            h0[6]=fmaf(xa,wA1.z,fmaf(xb,wB1.z,h0[6])); h0[7]=fmaf(xa,wA1.w,fmaf(xb,wB1.w,h0[7]));
            h1[0]=fmaf(xc,wA0.x,fmaf(xd,wB0.x,h1[0])); h1[1]=fmaf(xc,wA0.y,fmaf(xd,wB0.y,h1[1]));
            h1[2]=fmaf(xc,wA0.z,fmaf(xd,wB0.z,h1[2])); h1[3]=fmaf(xc,wA0.w,fmaf(xd,wB0.w,h1[3]));
            h1[4]=fmaf(xc,wA1.x,fmaf(xd,wB1.x,h1[4])); h1[5]=fmaf(xc,wA1.y,fmaf(xd,wB1.y,h1[5]));
            h1[6]=fmaf(xc,wA1.z,fmaf(xd,wB1.z,h1[6])); h1[7]=fmaf(xc,wA1.w,fmaf(xd,wB1.w,h1[7]));
        }
        #pragma unroll
        for (int j = 0; j < NP; j++) {
            h0[j] += __shfl_xor_sync(0xffffffffu, h0[j], 1);
            h0[j] += __shfl_xor_sync(0xffffffffu, h0[j], 2);
            h1[j] += __shfl_xor_sync(0xffffffffu, h1[j], 1);
            h1[j] += __shfl_xor_sync(0xffffffffu, h1[j], 2);
        }

        if (c == 0) {
            #pragma unroll
            for (int half = 0; half < 2; half++) {
                const float* hh = half ? h1 : h0;
                const int row = warp * 32 + mt * 16 + half * 8 + gr;
                const int pos = basE + row;

                float hv[NP];
                {
                    const float4 q0 = __ldg((const float4*)(b4));
                    const float4 q1 = __ldg((const float4*)(b4 + 4));
                    hv[0]=fmaxf(hh[0]+q0.x,0.f); hv[1]=fmaxf(hh[1]+q0.y,0.f);
                    hv[2]=fmaxf(hh[2]+q0.z,0.f); hv[3]=fmaxf(hh[3]+q0.w,0.f);
                    hv[4]=fmaxf(hh[4]+q1.x,0.f); hv[5]=fmaxf(hh[5]+q1.y,0.f);
                    hv[6]=fmaxf(hh[6]+q1.z,0.f); hv[7]=fmaxf(hh[7]+q1.w,0.f);
                }
                float g[NP];
                {
                    const float4 q0 = __ldg((const float4*)(b5));
                    const float4 q1 = __ldg((const float4*)(b5 + 4));
                    g[0]=q0.x; g[1]=q0.y; g[2]=q0.z; g[3]=q0.w;
                    g[4]=q1.x; g[5]=q1.y; g[6]=q1.z; g[7]=q1.w;
                }
                #pragma unroll
                for (int i = 0; i < NP; i++) {
                    const float x = hv[i];
                    const float4 r0v = __ldg((const float4*)(W5 + i*NP));
                    const float4 r1v = __ldg((const float4*)(W5 + i*NP + 4));
                    g[0]=fmaf(x,r0v.x,g[0]); g[1]=fmaf(x,r0v.y,g[1]);
                    g[2]=fmaf(x,r0v.z,g[2]); g[3]=fmaf(x,r0v.w,g[3]);
                    g[4]=fmaf(x,r1v.x,g[4]); g[5]=fmaf(x,r1v.y,g[5]);
                    g[6]=fmaf(x,r1v.z,g[6]); g[7]=fmaf(x,r1v.w,g[7]);
                }
                float res[NP];
                #pragma unroll
                for (int j = 1; j <= NP; j++) {
                    float f = __ldg(b6 + j);
                    #pragma unroll
                    for (int i = 0; i < NP; i++)
                        f = fmaf(g[i], __ldg(W6 + i * IN_D + j), f);
                    res[j-1] = s_in[row*12 + j] + f;
                }
                if (pos < k) {
                    float4* op = (float4*)(out + (size_t)pos * NP);
                    op[0] = make_float4(res[0], res[1], res[2], res[3]);
                    op[1] = make_float4(res[4], res[5], res[6], res[7]);
                }
            }
        }
    }
}

// ---------------- launch ----------------
extern "C" void kernel_launch(void* const* d_in, const int* in_sizes, int n_in,
                              void* d_out, int out_size)
{
    const float* data     = (const float*)d_in[0];
    const int*   elements = (const int*)  d_in[1];
    const float* W0 = (const float*)d_in[2];  const float* b0 = (const float*)d_in[3];
    const float* W1 = (const float*)d_in[4];  const float* b1 = (const float*)d_in[5];
    const float* W2 = (const float*)d_in[6];  const float* b2 = (const float*)d_in[7];
    const float* W3 = (const float*)d_in[8];  const float* b3 = (const float*)d_in[9];
    const float* W4 = (const float*)d_in[10]; const float* b4 = (const float*)d_in[11];
    const float* W5 = (const float*)d_in[12]; const float* b5 = (const float*)d_in[13];
    const float* W6 = (const float*)d_in[14]; const float* b6 = (const float*)d_in[15];
    float* out = (float*)d_out;

    const int k = in_sizes[1];

    prep_kernel<<<dim3(8, 4), 256>>>(W0, W1, W2, W3);

    const int grid = (k + TILE_M - 1) / TILE_M;
    const size_t smem = 77856u + 1024u;
    cudaFuncSetAttribute(ElementGNN_h2_kernel,
                         cudaFuncAttributeMaxDynamicSharedMemorySize, (int)smem);
    ElementGNN_h2_kernel<<<grid, THREADS, smem>>>(
        data, elements, b0, b1, b2, b3, W4, b4, W5, b5, W6, b6, out, k);
}

// round 7
// speedup vs baseline: 6.4442x; 1.4551x over previous
#include <cuda_runtime.h>
#include <cuda_fp16.h>
#include <stdint.h>

#define NP      8
#define NP1     9
#define IN_D    10
#define THREADS 128          // 4 compute warps, m32 each; warp 0 lane 0 drives copies
#define TILE_M  128

// Single-plane fp16 weight image, fragment-ordered:
//   L0 @ 0 (4KB) | L1 @ 4096 (32KB) | L2 @ 36864 (32KB) | L3 @ 69632 (32KB)
// Entry ((ks*8+ntp)*32+lane)*16B = {w0(nt=2ntp),w1(nt=2ntp),w0(nt=2ntp+1),w1(nt=2ntp+1)}
__device__ __align__(16) unsigned char g_W[102400];

// ---------------- helpers ----------------
__device__ __forceinline__ uint32_t smem_u32(const void* p){
    uint32_t a;
    asm("{ .reg .u64 t; cvta.to.shared.u64 t, %1; cvt.u32.u64 %0, t; }" : "=r"(a) : "l"(p));
    return a;
}
__device__ __forceinline__ uint32_t packf16(float x0, float x1){ // x0 -> low half
    uint32_t r; asm("cvt.rn.f16x2.f32 %0, %1, %2;" : "=r"(r) : "f"(x1), "f"(x0)); return r;
}

#define MBAR_INIT(a,c)   asm volatile("mbarrier.init.shared.b64 [%0], %1;" :: "r"(a), "r"(c) : "memory")
#define MBAR_EXPECT(a,b) asm volatile("mbarrier.arrive.expect_tx.shared.b64 _, [%0], %1;" :: "r"(a), "r"(b) : "memory")
#define MBAR_ARRIVE(a)   asm volatile("mbarrier.arrive.shared.b64 _, [%0];" :: "r"(a) : "memory")
#define FENCE_PROXY()    asm volatile("fence.proxy.async.shared::cta;" ::: "memory")

__device__ __forceinline__ void mbar_wait(uint32_t mbar, uint32_t parity){
    asm volatile(
        "{\n\t.reg .pred P;\n\t"
        "WL_%=:\n\t"
        "mbarrier.try_wait.parity.acquire.cta.shared::cta.b64 P, [%0], %1, 0x989680;\n\t"
        "@P bra.uni WD_%=;\n\t"
        "bra.uni WL_%=;\n\t"
        "WD_%=:\n\t}"
        :: "r"(mbar), "r"(parity) : "memory");
}
__device__ __forceinline__ void bulk_copy(uint32_t dst, const void* src, uint32_t bytes, uint32_t mbar){
    asm volatile(
        "cp.async.bulk.shared::cta.global.mbarrier::complete_tx::bytes [%0], [%1], %2, [%3];"
        :: "r"(dst), "l"(src), "r"(bytes), "r"(mbar) : "memory");
}

#define LDS128(r0,r1,r2,r3,addr) \
    asm volatile("ld.shared.v4.b32 {%0,%1,%2,%3}, [%4];" : "=r"(r0),"=r"(r1),"=r"(r2),"=r"(r3) : "r"(addr))

#define MMA_F16(C, a0,a1,a2,a3, b0,b1) \
    asm volatile("mma.sync.aligned.m16n8k16.row.col.f32.f16.f16.f32 " \
        "{%0,%1,%2,%3}, {%4,%5,%6,%7}, {%8,%9}, {%0,%1,%2,%3};" \
        : "+f"((C)[0]), "+f"((C)[1]), "+f"((C)[2]), "+f"((C)[3]) \
        : "r"(a0), "r"(a1), "r"(a2), "r"(a3), "r"(b0), "r"(b1))

// ---------------- weight prep (single fp16 plane) ----------------
__global__ void prep_kernel(const float* __restrict__ W0, const float* __restrict__ W1,
                            const float* __restrict__ W2, const float* __restrict__ W3)
{
    const int layer = blockIdx.y;
    const int idx   = blockIdx.x * 256 + threadIdx.x;   // (ks*8+ntp)*32+lane
    const int lane  = idx & 31;
    const int rest  = idx >> 5;
    const int ntp   = rest & 7;
    const int ks    = rest >> 3;                        // 0..7
    if (ks > 7) return;
    if (layer == 0 && ks > 0) return;

    const float* W = (layer == 0) ? W0 : (layer == 1) ? W1 : (layer == 2) ? W2 : W3;
    const int KMAX = (layer == 0) ? IN_D : 128;

    uint32_t hi[4];
    #pragma unroll
    for (int h = 0; h < 2; h++) {
        const int n  = (2*ntp + h) * 8 + (lane >> 2);
        const int t  = lane & 3;
        const int kb = ks * 16;
        const int kr[4] = { kb + 2*t, kb + 2*t + 1, kb + 2*t + 8, kb + 2*t + 9 };
        float v[4];
        #pragma unroll
        for (int i = 0; i < 4; i++)
            v[i] = (kr[i] < KMAX) ? __ldg(W + kr[i] * 128 + n) : 0.f;
        hi[2*h]   = packf16(v[0], v[1]);
        hi[2*h+1] = packf16(v[2], v[3]);
    }

    const size_t lbase = (layer == 0) ? 0 : (4096 + (size_t)(layer-1) * 32768);
    const size_t off   = (size_t)((ks*8 + ntp) * 32 + lane) * 16;
    *(uint4*)(&g_W[lbase + off]) = make_uint4(hi[0],hi[1],hi[2],hi[3]);
}

// ---------------- layer MMA: m32, single pass, 32-deep independence ----------------
template <int NKS>
__device__ __forceinline__ void run_layer(float acc[2][16][4],
                                          const uint32_t aH[2][8][4],
                                          uint32_t wbase, int lane)
{
    const uint32_t lof = (uint32_t)lane * 16u;
    #pragma unroll
    for (int ks = 0; ks < NKS; ks++) {
        uint32_t w[8][4];
        #pragma unroll
        for (int ntp = 0; ntp < 8; ntp++)
            LDS128(w[ntp][0],w[ntp][1],w[ntp][2],w[ntp][3],
                   wbase + (uint32_t)((ks*8 + ntp)*32)*16u + lof);
        #pragma unroll
        for (int ntp = 0; ntp < 8; ntp++) {
            #pragma unroll
            for (int mt = 0; mt < 2; mt++) {
                MMA_F16(acc[mt][2*ntp],   aH[mt][ks][0],aH[mt][ks][1],aH[mt][ks][2],aH[mt][ks][3], w[ntp][0],w[ntp][1]);
                MMA_F16(acc[mt][2*ntp+1], aH[mt][ks][0],aH[mt][ks][1],aH[mt][ks][2],aH[mt][ks][3], w[ntp][2],w[ntp][3]);
            }
        }
    }
}

// D frags + bias (+relu) -> next layer A frags (fp16); zeroes acc.
template <bool RELU>
__device__ __forceinline__ void make_A(float acc[2][16][4], uint32_t aH[2][8][4],
                                       const float* __restrict__ biasL, int c)
{
    #pragma unroll
    for (int mt = 0; mt < 2; mt++) {
        #pragma unroll
        for (int kt = 0; kt < 8; kt++) {
            #pragma unroll
            for (int h = 0; h < 2; h++) {
                const int nt = 2*kt + h;
                const float b0 = biasL[nt*8 + 2*c];
                const float b1 = biasL[nt*8 + 2*c + 1];
                float x0 = acc[mt][nt][0] + b0, x1 = acc[mt][nt][1] + b1;
                float x2 = acc[mt][nt][2] + b0, x3 = acc[mt][nt][3] + b1;
                if (RELU) {
                    x0 = fmaxf(x0,0.f); x1 = fmaxf(x1,0.f);
                    x2 = fmaxf(x2,0.f); x3 = fmaxf(x3,0.f);
                }
                aH[mt][kt][2*h]   = packf16(x0, x1);
                aH[mt][kt][2*h+1] = packf16(x2, x3);
                acc[mt][nt][0]=0.f; acc[mt][nt][1]=0.f; acc[mt][nt][2]=0.f; acc[mt][nt][3]=0.f;
            }
        }
    }
}

// ---------------- main kernel ----------------
__global__ void __launch_bounds__(THREADS, 2)
ElementGNN_h1_kernel(const float* __restrict__ data,
                     const int*   __restrict__ elements,
                     const float* __restrict__ b0, const float* __restrict__ b1,
                     const float* __restrict__ b2, const float* __restrict__ b3,
                     const float* __restrict__ W4, const float* __restrict__ b4,
                     const float* __restrict__ W5, const float* __restrict__ b5,
                     const float* __restrict__ W6, const float* __restrict__ b6,
                     float* __restrict__ out, int k)
{
    extern __shared__ char smraw[];
    const uint32_t raw = smem_u32(smraw);
    const uint32_t s0  = (raw + 1023u) & ~1023u;
    char* base = smraw + (s0 - raw);

    const uint32_t wBuf0 = s0;                 // 32KB
    const uint32_t wBuf1 = s0 + 32768u;        // 32KB
    float* s_in  = (float*)(base + 65536);     // [128][12] fp32 (6144B)
    float* sBias = (float*)(base + 71680);     // [4][128]      (2048B)
    float* sW4   = (float*)(base + 73728);     // [128][8]      (4096B)
    float* sW5   = (float*)(base + 77824);     // [8][8]        (256B)
    float* sW6   = (float*)(base + 78080);     // [8][10]       (320B)
    const uint32_t full0  = s0 + 78400u;
    const uint32_t full1  = s0 + 78408u;
    const uint32_t empty0 = s0 + 78416u;
    const uint32_t empty1 = s0 + 78424u;

    const int tid  = threadIdx.x;
    const int warp = tid >> 5;
    const int lane = tid & 31;
    const int basE = blockIdx.x * TILE_M;

    if (tid == 0) {
        MBAR_INIT(full0, 1);  MBAR_INIT(full1, 1);
        MBAR_INIT(empty0, 4); MBAR_INIT(empty1, 4);
        FENCE_PROXY();
    }
    __syncthreads();
    if (tid == 0) {
        MBAR_EXPECT(full0, 4096u);  bulk_copy(wBuf0, &g_W[0],    4096u,  full0);  // L0
        MBAR_EXPECT(full1, 32768u); bulk_copy(wBuf1, &g_W[4096], 32768u, full1);  // L1
    }

    // ---- gather (128 rows) + bias + tail-weight staging ----
    {
        const int m = tid, pos = basE + m;
        float v[IN_D];
        #pragma unroll
        for (int j = 0; j < IN_D; j++) v[j] = 0.f;
        if (pos < k) {
            const int e  = elements[pos] / NP1;
            const int le = (e == 0) ? (k - 1) : (e - 1);
            const int ri = (e == k - 1) ? 0 : (e + 1);
            const float4 a0 = __ldg((const float4*)(data + (size_t)e * NP));
            const float4 a1 = __ldg((const float4*)(data + (size_t)e * NP + 4));
            v[0] = __ldg(data + (size_t)le * NP + (NP - 1));
            v[1]=a0.x; v[2]=a0.y; v[3]=a0.z; v[4]=a0.w;
            v[5]=a1.x; v[6]=a1.y; v[7]=a1.z; v[8]=a1.w;
            v[9] = __ldg(data + (size_t)ri * NP);
        }
        #pragma unroll
        for (int j = 0; j < IN_D; j++) s_in[m*12 + j] = v[j];
        sBias[0*128 + m] = __ldg(b0 + m);
        sBias[1*128 + m] = __ldg(b1 + m);
        sBias[2*128 + m] = __ldg(b2 + m);
        sBias[3*128 + m] = __ldg(b3 + m);
        #pragma unroll
        for (int i = m; i < 128*NP; i += THREADS) sW4[i] = __ldg(W4 + i);
        if (m < 64) sW5[m] = __ldg(W5 + m);
        if (m < 80) sW6[m] = __ldg(W6 + m);
    }
    __syncthreads();

    // ---- per-warp layer-0 A frags (m32 = 2 m16 tiles) ----
    const int gr = lane >> 2, c = lane & 3;

    uint32_t aH[2][8][4];
    #pragma unroll
    for (int mt = 0; mt < 2; mt++) {
        const int r0 = warp * 32 + mt * 16 + gr;   // rows r0, r0+8
        const int cols[4] = { 2*c, 2*c+1, 2*c+8, 2*c+9 };
        float f0[4], f1[4];
        #pragma unroll
        for (int i = 0; i < 4; i++) {
            f0[i] = (cols[i] < IN_D) ? s_in[r0*12 + cols[i]]     : 0.f;
            f1[i] = (cols[i] < IN_D) ? s_in[(r0+8)*12 + cols[i]] : 0.f;
        }
        aH[mt][0][0] = packf16(f0[0], f0[1]);
        aH[mt][0][1] = packf16(f1[0], f1[1]);
        aH[mt][0][2] = packf16(f0[2], f0[3]);
        aH[mt][0][3] = packf16(f1[2], f1[3]);
    }

    float acc[2][16][4];
    #pragma unroll
    for (int mt = 0; mt < 2; mt++)
        #pragma unroll
        for (int i = 0; i < 16; i++) {
            acc[mt][i][0]=0.f; acc[mt][i][1]=0.f; acc[mt][i][2]=0.f; acc[mt][i][3]=0.f;
        }

    const bool prod = (warp == 0 && lane == 0);

    // L0 : buf0 @ p0 (K=16, relu)
    mbar_wait(full0, 0);
    run_layer<1>(acc, aH, wBuf0, lane);
    __syncwarp(); if (lane == 0) MBAR_ARRIVE(empty0);
    if (prod) { mbar_wait(empty0, 0);
        MBAR_EXPECT(full0, 32768u); bulk_copy(wBuf0, &g_W[36864], 32768u, full0); } // L2
    make_A<true>(acc, aH, sBias + 0*128, c);

    // L1 : buf1 @ p0
    mbar_wait(full1, 0);
    run_layer<8>(acc, aH, wBuf1, lane);
    __syncwarp(); if (lane == 0) MBAR_ARRIVE(empty1);
    if (prod) { mbar_wait(empty1, 0);
        MBAR_EXPECT(full1, 32768u); bulk_copy(wBuf1, &g_W[69632], 32768u, full1); } // L3
    make_A<false>(acc, aH, sBias + 1*128, c);

    // L2 : buf0 @ p1 (relu)
    mbar_wait(full0, 1);
    run_layer<8>(acc, aH, wBuf0, lane);
    make_A<true>(acc, aH, sBias + 2*128, c);

    // L3 : buf1 @ p1
    mbar_wait(full1, 1);
    run_layer<8>(acc, aH, wBuf1, lane);

    // ---- tail per m16 tile: bias3 + GEMV 128->8, quad reduce, scalar finish ----
    const float* bias3 = sBias + 3*128;
    #pragma unroll
    for (int mt = 0; mt < 2; mt++) {
        float h0[NP], h1[NP];
        #pragma unroll
        for (int j = 0; j < NP; j++) { h0[j]=0.f; h1[j]=0.f; }
        #pragma unroll
        for (int nt = 0; nt < 16; nt++) {
            const float bb0 = bias3[nt*8 + 2*c], bb1 = bias3[nt*8 + 2*c + 1];
            const float xa = acc[mt][nt][0]+bb0, xb = acc[mt][nt][1]+bb1;
            const float xc = acc[mt][nt][2]+bb0, xd = acc[mt][nt][3]+bb1;
            const int col0 = nt*8 + 2*c;
            const float4 wA0 = *(const float4*)(sW4 + col0*NP);
            const float4 wA1 = *(const float4*)(sW4 + col0*NP + 4);
            const float4 wB0 = *(const float4*)(sW4 + (col0+1)*NP);
            const float4 wB1 = *(const float4*)(sW4 + (col0+1)*NP + 4);
            h0[0]=fmaf(xa,wA0.x,fmaf(xb,wB0.x,h0[0])); h0[1]=fmaf(xa,wA0.y,fmaf(xb,wB0.y,h0[1]));
            h0[2]=fmaf(xa,wA0.z,fmaf(xb,wB0.z,h0[2])); h0[3]=fmaf(xa,wA0.w,fmaf(xb,wB0.w,h0[3]));
            h0[4]=fmaf(xa,wA1.x,fmaf(xb,wB1.x,h0[4])); h0[5]=fmaf(xa,wA1.y,fmaf(xb,wB1.y,h0[5]));
            h0[6]=fmaf(xa,wA1.z,fmaf(xb,wB1.z,h0[6])); h0[7]=fmaf(xa,wA1.w,fmaf(xb,wB1.w,h0[7]));
            h1[0]=fmaf(xc,wA0.x,fmaf(xd,wB0.x,h1[0])); h1[1]=fmaf(xc,wA0.y,fmaf(xd,wB0.y,h1[1]));
            h1[2]=fmaf(xc,wA0.z,fmaf(xd,wB0.z,h1[2])); h1[3]=fmaf(xc,wA0.w,fmaf(xd,wB0.w,h1[3]));
            h1[4]=fmaf(xc,wA1.x,fmaf(xd,wB1.x,h1[4])); h1[5]=fmaf(xc,wA1.y,fmaf(xd,wB1.y,h1[5]));
            h1[6]=fmaf(xc,wA1.z,fmaf(xd,wB1.z,h1[6])); h1[7]=fmaf(xc,wA1.w,fmaf(xd,wB1.w,h1[7]));
        }
        #pragma unroll
        for (int j = 0; j < NP; j++) {
            h0[j] += __shfl_xor_sync(0xffffffffu, h0[j], 1);
            h0[j] += __shfl_xor_sync(0xffffffffu, h0[j], 2);
            h1[j] += __shfl_xor_sync(0xffffffffu, h1[j], 1);
            h1[j] += __shfl_xor_sync(0xffffffffu, h1[j], 2);
        }

        if (c == 0) {
            #pragma unroll
            for (int half = 0; half < 2; half++) {
                const float* hh = half ? h1 : h0;
                const int row = warp * 32 + mt * 16 + half * 8 + gr;
                const int pos = basE + row;

                float hv[NP];
                {
                    const float4 q0 = __ldg((const float4*)(b4));
                    const float4 q1 = __ldg((const float4*)(b4 + 4));
                    hv[0]=fmaxf(hh[0]+q0.x,0.f); hv[1]=fmaxf(hh[1]+q0.y,0.f);
                    hv[2]=fmaxf(hh[2]+q0.z,0.f); hv[3]=fmaxf(hh[3]+q0.w,0.f);
                    hv[4]=fmaxf(hh[4]+q1.x,0.f); hv[5]=fmaxf(hh[5]+q1.y,0.f);
                    hv[6]=fmaxf(hh[6]+q1.z,0.f); hv[7]=fmaxf(hh[7]+q1.w,0.f);
                }
                float g[NP];
                {
                    const float4 q0 = __ldg((const float4*)(b5));
                    const float4 q1 = __ldg((const float4*)(b5 + 4));
                    g[0]=q0.x; g[1]=q0.y; g[2]=q0.z; g[3]=q0.w;
                    g[4]=q1.x; g[5]=q1.y; g[6]=q1.z; g[7]=q1.w;
                }
                #pragma unroll
                for (int i = 0; i < NP; i++) {
                    const float x = hv[i];
                    const float4 r0v = *(const float4*)(sW5 + i*NP);
                    const float4 r1v = *(const float4*)(sW5 + i*NP + 4);
                    g[0]=fmaf(x,r0v.x,g[0]); g[1]=fmaf(x,r0v.y,g[1]);
                    g[2]=fmaf(x,r0v.z,g[2]); g[3]=fmaf(x,r0v.w,g[3]);
                    g[4]=fmaf(x,r1v.x,g[4]); g[5]=fmaf(x,r1v.y,g[5]);
                    g[6]=fmaf(x,r1v.z,g[6]); g[7]=fmaf(x,r1v.w,g[7]);
                }
                float res[NP];
                #pragma unroll
                for (int j = 1; j <= NP; j++) {
                    float f = __ldg(b6 + j);
                    #pragma unroll
                    for (int i = 0; i < NP; i++)
                        f = fmaf(g[i], sW6[i * IN_D + j], f);
                    res[j-1] = s_in[row*12 + j] + f;
                }
                if (pos < k) {
                    float4* op = (float4*)(out + (size_t)pos * NP);
                    op[0] = make_float4(res[0], res[1], res[2], res[3]);
                    op[1] = make_float4(res[4], res[5], res[6], res[7]);
                }
            }
        }
    }
}

// ---------------- launch ----------------
extern "C" void kernel_launch(void* const* d_in, const int* in_sizes, int n_in,
                              void* d_out, int out_size)
{
    const float* data     = (const float*)d_in[0];
    const int*   elements = (const int*)  d_in[1];
    const float* W0 = (const float*)d_in[2];  const float* b0 = (const float*)d_in[3];
    const float* W1 = (const float*)d_in[4];  const float* b1 = (const float*)d_in[5];
    const float* W2 = (const float*)d_in[6];  const float* b2 = (const float*)d_in[7];
    const float* W3 = (const float*)d_in[8];  const float* b3 = (const float*)d_in[9];
    const float* W4 = (const float*)d_in[10]; const float* b4 = (const float*)d_in[11];
    const float* W5 = (const float*)d_in[12]; const float* b5 = (const float*)d_in[13];
    const float* W6 = (const float*)d_in[14]; const float* b6 = (const float*)d_in[15];
    float* out = (float*)d_out;

    const int k = in_sizes[1];

    prep_kernel<<<dim3(8, 4), 256>>>(W0, W1, W2, W3);

    const int grid = (k + TILE_M - 1) / TILE_M;
    const size_t smem = 78432u + 1024u;
    cudaFuncSetAttribute(ElementGNN_h1_kernel,
                         cudaFuncAttributeMaxDynamicSharedMemorySize, (int)smem);
    ElementGNN_h1_kernel<<<grid, THREADS, smem>>>(
        data, elements, b0, b1, b2, b3, W4, b4, W5, b5, W6, b6, out, k);
}